// round 1
// baseline (speedup 1.0000x reference)
#include <cuda_runtime.h>
#include <math.h>

// Problem constants
#define BSZ  32
#define NTOK 320
#define CDIM 768
#define HN   12
#define STOK 256
#define TTOK 64
#define HD   64

// ---------------- scratch (__device__ globals: allocation-free) --------------
__device__ float g_tgt[BSZ * CDIM];                      // [B,C]
__device__ float g_min[BSZ * STOK * 2 * CDIM];           // [B*S, 1536]
__device__ float g_h1 [BSZ * STOK * 384];                // [B*S, 384]
__device__ float g_h2 [BSZ * STOK * 192];                // [B*S, 192]
__device__ int   g_grp[BSZ * NTOK];                      // token group 0/1/2
__device__ float g_qkv[BSZ * NTOK * 3 * CDIM];           // [B*N, 2304]
__device__ float g_S  [(size_t)BSZ * HN * NTOK * NTOK];  // [B*H, 320, 320]
__device__ float g_ao [BSZ * NTOK * CDIM];               // attn out pre-proj

__device__ __forceinline__ float gelu_exact(float v) {
    return 0.5f * v * (1.0f + erff(v * 0.70710678118654752f));
}

// ---------------- generic tiled SGEMM: C = alpha * A * B^T + bias ------------
// A[m][k] = A[m*aRow + k]           (aK == 1 always in this kernel's uses)
// B[n][k] = B[n*bN + k*bK]          (bK==1 fast path, bN==1 slow path)
// Two-level batch: z -> (zo, zi) with zi = z % innerCount
// act: 0 = none, 1 = exact GELU
__global__ __launch_bounds__(256)
void sgemm_kernel(const float* __restrict__ A, const float* __restrict__ B,
                  const float* __restrict__ bias, float* __restrict__ C,
                  int M, int N, int K,
                  int aRow, int bN, int bK, int ldc,
                  int innerCount,
                  long long aOuter, long long aInner,
                  long long bOuter, long long bInner,
                  long long cOuter, long long cInner,
                  float alpha, int act)
{
    int z  = blockIdx.z;
    int zo = z / innerCount, zi = z % innerCount;
    A += (long long)zo * aOuter + (long long)zi * aInner;
    B += (long long)zo * bOuter + (long long)zi * bInner;
    C += (long long)zo * cOuter + (long long)zi * cInner;

    __shared__ float As[16][64];
    __shared__ float Bs[16][64];

    const int t  = threadIdx.x;      // 0..255
    const int ty = t >> 4;           // 0..15 (row group)
    const int tx = t & 15;           // 0..15 (col group)
    const int m0 = blockIdx.y * 64;
    const int n0 = blockIdx.x * 64;

    const int rl = t >> 2;           // 0..63 row/col for tile loads
    const int kl = (t & 3) * 4;      // 0,4,8,12

    float acc[4][4];
#pragma unroll
    for (int i = 0; i < 4; i++)
#pragma unroll
        for (int j = 0; j < 4; j++) acc[i][j] = 0.0f;

    for (int k0 = 0; k0 < K; k0 += 16) {
        // --- A tile (aK == 1): float4 along K, transpose into As[kk][m]
        {
            const float4 av = *(const float4*)(A + (long long)(m0 + rl) * aRow + k0 + kl);
            As[kl + 0][rl] = av.x;
            As[kl + 1][rl] = av.y;
            As[kl + 2][rl] = av.z;
            As[kl + 3][rl] = av.w;
        }
        // --- B tile
        if (bK == 1) {
            const float4 bv = *(const float4*)(B + (long long)(n0 + rl) * bN + k0 + kl);
            Bs[kl + 0][rl] = bv.x;
            Bs[kl + 1][rl] = bv.y;
            Bs[kl + 2][rl] = bv.z;
            Bs[kl + 3][rl] = bv.w;
        } else { // bN == 1: B[n][k] at B[k*bK + n]; coalesce along n
#pragma unroll
            for (int l = 0; l < 4; l++) {
                int idx = t + l * 256;
                int kk = idx >> 6;
                int nn = idx & 63;
                Bs[kk][nn] = B[(long long)(k0 + kk) * bK + (n0 + nn)];
            }
        }
        __syncthreads();

#pragma unroll
        for (int kk = 0; kk < 16; kk++) {
            const float4 a4 = *(const float4*)(&As[kk][ty * 4]);
            const float4 b4 = *(const float4*)(&Bs[kk][tx * 4]);
            float a[4] = {a4.x, a4.y, a4.z, a4.w};
            float b[4] = {b4.x, b4.y, b4.z, b4.w};
#pragma unroll
            for (int i = 0; i < 4; i++)
#pragma unroll
                for (int j = 0; j < 4; j++) acc[i][j] += a[i] * b[j];
        }
        __syncthreads();
    }

    float bv[4] = {0.f, 0.f, 0.f, 0.f};
    if (bias) {
#pragma unroll
        for (int j = 0; j < 4; j++) bv[j] = bias[n0 + tx * 4 + j];
    }
#pragma unroll
    for (int i = 0; i < 4; i++) {
        int m = m0 + ty * 4 + i;
        if (m < M) {
#pragma unroll
            for (int j = 0; j < 4; j++) {
                int n = n0 + tx * 4 + j;
                float v = acc[i][j] * alpha + bv[j];
                if (act == 1) v = gelu_exact(v);
                C[(long long)m * ldc + n] = v;
            }
        }
    }
}

// ---------------- tgt_rep: masked mean over 64 template tokens ---------------
__global__ void tgt_kernel(const float* __restrict__ x, const float* __restrict__ mask)
{
    __shared__ float sm[TTOK];
    int b = blockIdx.x;
    if (threadIdx.x < TTOK) sm[threadIdx.x] = mask[b * TTOK + threadIdx.x];
    __syncthreads();
    for (int c = threadIdx.x; c < CDIM; c += blockDim.x) {
        float s = 0.0f;
        const float* xb = x + (long long)b * NTOK * CDIM + c;
#pragma unroll 8
        for (int t = 0; t < TTOK; t++) s += xb[(long long)t * CDIM] * sm[t];
        g_tgt[b * CDIM + c] = s * (1.0f / (float)TTOK);
    }
}

// ---------------- build MLP input: [x_search | tgt_rep] ----------------------
__global__ void minprep_kernel(const float* __restrict__ x)
{
    long long idx = (long long)blockIdx.x * blockDim.x + threadIdx.x;
    const long long total = (long long)BSZ * STOK * 2 * CDIM;
    if (idx >= total) return;
    int c   = (int)(idx % (2 * CDIM));
    int tok = (int)(idx / (2 * CDIM));
    int b = tok / STOK, s = tok % STOK;
    float v;
    if (c < CDIM) v = x[((long long)b * NTOK + (TTOK + s)) * CDIM + c];
    else          v = g_tgt[b * CDIM + (c - CDIM)];
    g_min[idx] = v;
}

// ---------------- final MLP layer + argmax + groups + decision out -----------
__global__ void decide_kernel(const float* __restrict__ dp3_w,
                              const float* __restrict__ dp3_b,
                              float* dec_out)
{
    int idx = blockIdx.x * blockDim.x + threadIdx.x;
    if (idx >= BSZ * NTOK) return;
    int b = idx / NTOK, tok = idx % NTOK;
    if (tok < TTOK) { g_grp[idx] = 0; return; }
    int s = tok - TTOK;
    const float* h = g_h2 + ((long long)b * STOK + s) * 192;
    float l0 = dp3_b[0], l1 = dp3_b[1];
#pragma unroll 4
    for (int k = 0; k < 192; k++) {
        float hv = h[k];
        l0 += hv * dp3_w[k];
        l1 += hv * dp3_w[192 + k];
    }
    int cls = (l1 > l0) ? 1 : 0;          // argmax (first index wins ties)
    g_grp[idx] = 1 + cls;
    if (dec_out) {
        long long o = ((long long)b * STOK + s) * 2;
        dec_out[o + 0] = (cls == 0) ? 1.0f : 0.0f;
        dec_out[o + 1] = (cls == 1) ? 1.0f : 0.0f;
    }
}

// ---------------- policy softmax (in-place on g_S), one warp per row ---------
__global__ void softmax_policy_kernel()
{
    const int warp = threadIdx.x >> 5;
    const int lane = threadIdx.x & 31;
    const long long r = (long long)blockIdx.x * 4 + warp;   // row id
    const long long nrows = (long long)BSZ * HN * NTOK;
    if (r >= nrows) return;
    int bh = (int)(r / NTOK);
    int i  = (int)(r % NTOK);
    int b  = bh / HN;
    float* row = g_S + (long long)bh * NTOK * NTOK + (long long)i * NTOK;
    const int* grp = g_grp + b * NTOK;
    int gi = grp[i];

    float sv[10];
    float mx = -3.4e38f;
#pragma unroll
    for (int l = 0; l < 10; l++) {
        sv[l] = row[lane + l * 32];
        mx = fmaxf(mx, sv[l]);
    }
#pragma unroll
    for (int o = 16; o > 0; o >>= 1) mx = fmaxf(mx, __shfl_xor_sync(0xffffffffu, mx, o));

    float sum = 0.0f;
#pragma unroll
    for (int l = 0; l < 10; l++) {
        int j = lane + l * 32;
        int gj = grp[j];
        float m = (gi == 2 || gj == 2 || gi == gj) ? 1.0f : 0.0f;
        float e = expf(sv[l] - mx) * m;
        sv[l] = e;
        sum += e;
    }
#pragma unroll
    for (int o = 16; o > 0; o >>= 1) sum += __shfl_xor_sync(0xffffffffu, sum, o);

    const float epsn = 1e-6f / (float)NTOK;
    float inv = 1.0f / (sum + 1e-6f);
#pragma unroll
    for (int l = 0; l < 10; l++) row[lane + l * 32] = (sv[l] + epsn) * inv;
}

// ---------------- host launcher ----------------------------------------------
extern "C" void kernel_launch(void* const* d_in, const int* in_sizes, int n_in,
                              void* d_out, int out_size)
{
    const float* x      = (const float*)d_in[0];
    const float* tmask  = (const float*)d_in[1];
    const float* qkv_w  = (const float*)d_in[2];
    const float* qkv_b  = (const float*)d_in[3];
    const float* proj_w = (const float*)d_in[4];
    const float* proj_b = (const float*)d_in[5];
    const float* dp1_w  = (const float*)d_in[6];
    const float* dp1_b  = (const float*)d_in[7];
    const float* dp2_w  = (const float*)d_in[8];
    const float* dp2_b  = (const float*)d_in[9];
    const float* dp3_w  = (const float*)d_in[10];
    const float* dp3_b  = (const float*)d_in[11];
    float* out = (float*)d_out;

    // decision output region (tuple concat), guarded by out_size
    const long long OUT_MAIN = (long long)BSZ * NTOK * CDIM;   // 7,864,320
    const long long OUT_DEC  = (long long)BSZ * STOK * 2;      //    16,384
    float* dec_out = ((long long)out_size >= OUT_MAIN + OUT_DEC) ? (out + OUT_MAIN) : nullptr;

    float *p_tgt, *p_min, *p_h1, *p_h2, *p_qkv, *p_S, *p_ao;
    cudaGetSymbolAddress((void**)&p_tgt, g_tgt);
    cudaGetSymbolAddress((void**)&p_min, g_min);
    cudaGetSymbolAddress((void**)&p_h1,  g_h1);
    cudaGetSymbolAddress((void**)&p_h2,  g_h2);
    cudaGetSymbolAddress((void**)&p_qkv, g_qkv);
    cudaGetSymbolAddress((void**)&p_S,   g_S);
    cudaGetSymbolAddress((void**)&p_ao,  g_ao);

    // 1) tgt representation
    tgt_kernel<<<BSZ, 256>>>(x, tmask);

    // 2) MLP input concat
    {
        long long total = (long long)BSZ * STOK * 2 * CDIM;
        int blocks = (int)((total + 255) / 256);
        minprep_kernel<<<blocks, 256>>>(x);
    }

    // 3) QKV GEMM: [10240,768] x [2304,768]^T -> [10240,2304]
    sgemm_kernel<<<dim3(2304 / 64, (BSZ * NTOK) / 64, 1), 256>>>(
        x, qkv_w, qkv_b, p_qkv,
        BSZ * NTOK, 3 * CDIM, CDIM,
        CDIM, CDIM, 1, 3 * CDIM,
        1, 0, 0, 0, 0, 0, 0, 1.0f, 0);

    // 4) MLP layer1: [8192,1536] x [384,1536]^T + GELU
    sgemm_kernel<<<dim3(384 / 64, (BSZ * STOK) / 64, 1), 256>>>(
        p_min, dp1_w, dp1_b, p_h1,
        BSZ * STOK, 384, 2 * CDIM,
        2 * CDIM, 2 * CDIM, 1, 384,
        1, 0, 0, 0, 0, 0, 0, 1.0f, 1);

    // 5) MLP layer2: [8192,384] x [192,384]^T + GELU
    sgemm_kernel<<<dim3(192 / 64, (BSZ * STOK) / 64, 1), 256>>>(
        p_h1, dp2_w, dp2_b, p_h2,
        BSZ * STOK, 192, 384,
        384, 384, 1, 192,
        1, 0, 0, 0, 0, 0, 0, 1.0f, 1);

    // 6) decision + groups (+ decision output)
    decide_kernel<<<(BSZ * NTOK + 255) / 256, 256>>>(dp3_w, dp3_b, dec_out);

    // 7) S = Q K^T * scale, batched over (b,h)
    {
        long long aOuter = (long long)NTOK * 3 * CDIM;   // per-b
        long long strS   = (long long)NTOK * NTOK;
        sgemm_kernel<<<dim3(NTOK / 64, NTOK / 64, BSZ * HN), 256>>>(
            p_qkv, p_qkv + CDIM /*K block*/, nullptr, p_S,
            NTOK, NTOK, HD,
            3 * CDIM, 3 * CDIM, 1, NTOK,
            HN,
            aOuter, HD,          // A: b-stride, h-stride (Q)
            aOuter, HD,          // B: b-stride, h-stride (K)
            (long long)HN * strS, strS,
            0.125f /* hd^-0.5 */, 0);
    }

    // 8) policy softmax (in place on g_S)
    {
        long long nrows = (long long)BSZ * HN * NTOK;
        int blocks = (int)((nrows + 3) / 4);
        softmax_policy_kernel<<<blocks, 128>>>();
    }

    // 9) O = P V, batched over (b,h); V accessed transposed (bN==1 path)
    {
        long long strS = (long long)NTOK * NTOK;
        sgemm_kernel<<<dim3(HD / 64, NTOK / 64, BSZ * HN), 256>>>(
            p_S, p_qkv + 2 * CDIM /*V block*/, nullptr, p_ao,
            NTOK, HD, NTOK,
            NTOK, 1, 3 * CDIM, CDIM,
            HN,
            (long long)HN * strS, strS,                       // A = P
            (long long)NTOK * 3 * CDIM, HD,                   // B = V (transposed access)
            (long long)NTOK * CDIM, HD,                       // C = [b, i, h*64+d]
            1.0f, 0);
    }

    // 10) output projection: [10240,768] x [768,768]^T + bias -> d_out
    sgemm_kernel<<<dim3(CDIM / 64, (BSZ * NTOK) / 64, 1), 256>>>(
        p_ao, proj_w, proj_b, out,
        BSZ * NTOK, CDIM, CDIM,
        CDIM, CDIM, 1, CDIM,
        1, 0, 0, 0, 0, 0, 0, 1.0f, 0);
}

// round 2
// speedup vs baseline: 1.5607x; 1.5607x over previous
#include <cuda_runtime.h>
#include <cuda_bf16.h>
#include <math.h>

// Problem constants
#define BSZ  32
#define NTOK 320
#define CDIM 768
#define HN   12
#define STOK 256
#define TTOK 64
#define HD   64

// ---------------- scratch (__device__ globals: allocation-free) --------------
__device__ float g_tgt[BSZ * CDIM];                      // [B,C]
__device__ float g_min[BSZ * STOK * 2 * CDIM];           // [B*S, 1536]
__device__ float g_h1 [BSZ * STOK * 384];                // [B*S, 384]
__device__ float g_h2 [BSZ * STOK * 192];                // [B*S, 192]
__device__ int   g_grp[BSZ * NTOK];                      // token group 0/1/2
__device__ float g_qkv[BSZ * NTOK * 3 * CDIM];           // [B*N, 2304]
__device__ float g_S  [(size_t)BSZ * HN * NTOK * NTOK];  // [B*H, 320, 320]
__device__ float g_ao [BSZ * NTOK * CDIM];               // attn out pre-proj

__device__ __forceinline__ float gelu_exact(float v) {
    return 0.5f * v * (1.0f + erff(v * 0.70710678118654752f));
}

// ================= bf16x3 split-precision tensor-core GEMM ===================
// C = alpha * A * op(B) + bias
// A: [M,K] row-major, leading dim lda.
// bMode 0: B[n][k] (k contiguous, ld = ldb)  -> covers weights / K-matrix
// bMode 1: B[k][n] (n contiguous, ld = ldb)  -> covers V
// Two-level batch over blockIdx.z like the fp32 kernel.

__device__ __forceinline__ void split2(float x0, float x1, unsigned& hi, unsigned& lo) {
    __nv_bfloat16 h0 = __float2bfloat16(x0);
    __nv_bfloat16 h1 = __float2bfloat16(x1);
    float r0 = x0 - __bfloat162float(h0);
    float r1 = x1 - __bfloat162float(h1);
    __nv_bfloat16 l0 = __float2bfloat16(r0);
    __nv_bfloat16 l1 = __float2bfloat16(r1);
    hi = (unsigned)__bfloat16_as_ushort(h0) | ((unsigned)__bfloat16_as_ushort(h1) << 16);
    lo = (unsigned)__bfloat16_as_ushort(l0) | ((unsigned)__bfloat16_as_ushort(l1) << 16);
}

__device__ __forceinline__ void mma16816(float* c, const unsigned* a, const unsigned* b) {
    asm volatile(
        "mma.sync.aligned.m16n8k16.row.col.f32.bf16.bf16.f32 "
        "{%0,%1,%2,%3}, {%4,%5,%6,%7}, {%8,%9}, {%0,%1,%2,%3};\n"
        : "+f"(c[0]), "+f"(c[1]), "+f"(c[2]), "+f"(c[3])
        : "r"(a[0]), "r"(a[1]), "r"(a[2]), "r"(a[3]), "r"(b[0]), "r"(b[1]));
}

#define SPAD 132   // 128 + 4 padding (uint32 lanes)

__global__ __launch_bounds__(256, 2)
void mma_gemm_kernel(const float* __restrict__ A, const float* __restrict__ B,
                     const float* __restrict__ bias, float* __restrict__ C,
                     int M, int N, int K, int lda, int ldb, int ldc,
                     int bMode, int innerCount,
                     long long aOuter, long long aInner,
                     long long bOuter, long long bInner,
                     long long cOuter, long long cInner,
                     float alpha)
{
    int z  = blockIdx.z;
    int zo = z / innerCount, zi = z % innerCount;
    A += (long long)zo * aOuter + (long long)zi * aInner;
    B += (long long)zo * bOuter + (long long)zi * bInner;
    C += (long long)zo * cOuter + (long long)zi * cInner;

    __shared__ unsigned AsHi[8][SPAD], AsLo[8][SPAD];
    __shared__ unsigned BsHi[8][SPAD], BsLo[8][SPAD];

    const int t    = threadIdx.x;
    const int lane = t & 31;
    const int warp = t >> 5;
    const int wm   = warp >> 2;        // 0..1
    const int wn   = warp & 3;         // 0..3
    const int g    = lane >> 2;        // 0..7
    const int tg   = lane & 3;         // 0..3
    const int m0   = blockIdx.y * 128;
    const int n0   = blockIdx.x * 128;

    float acc[4][4][4];
#pragma unroll
    for (int i = 0; i < 4; i++)
#pragma unroll
        for (int j = 0; j < 4; j++)
#pragma unroll
            for (int r = 0; r < 4; r++) acc[i][j][r] = 0.0f;

    for (int k0 = 0; k0 < K; k0 += 16) {
        // ---- fill A slab: rows m0..m0+127, k k0..k0+15, packed pairs along k
#pragma unroll
        for (int l = 0; l < 2; l++) {
            int it  = t * 2 + l;          // 0..511
            int row = it >> 2;            // 0..127
            int f4  = it & 3;             // 0..3 -> k offset f4*4
            int m   = m0 + row;
            float4 v = make_float4(0.f, 0.f, 0.f, 0.f);
            if (m < M) v = *(const float4*)(A + (long long)m * lda + k0 + f4 * 4);
            unsigned h0, l0, h1, l1;
            split2(v.x, v.y, h0, l0);
            split2(v.z, v.w, h1, l1);
            AsHi[f4 * 2 + 0][row] = h0; AsLo[f4 * 2 + 0][row] = l0;
            AsHi[f4 * 2 + 1][row] = h1; AsLo[f4 * 2 + 1][row] = l1;
        }
        // ---- fill B slab
        if (bMode == 0) {
            // B[n][k], k contiguous
#pragma unroll
            for (int l = 0; l < 2; l++) {
                int it  = t * 2 + l;
                int row = it >> 2;        // n within tile
                int f4  = it & 3;
                int n   = n0 + row;
                float4 v = make_float4(0.f, 0.f, 0.f, 0.f);
                if (n < N) v = *(const float4*)(B + (long long)n * ldb + k0 + f4 * 4);
                unsigned h0, l0, h1, l1;
                split2(v.x, v.y, h0, l0);
                split2(v.z, v.w, h1, l1);
                BsHi[f4 * 2 + 0][row] = h0; BsLo[f4 * 2 + 0][row] = l0;
                BsHi[f4 * 2 + 1][row] = h1; BsLo[f4 * 2 + 1][row] = l1;
            }
        } else {
            // B[k][n], n contiguous: pack vertically across two k rows
            int k2  = t >> 5;             // 0..7
            int f4n = t & 31;             // 0..31
            int n   = n0 + f4n * 4;
            float4 r0 = make_float4(0.f, 0.f, 0.f, 0.f);
            float4 r1 = make_float4(0.f, 0.f, 0.f, 0.f);
            if (n < N) {
                r0 = *(const float4*)(B + (long long)(k0 + 2 * k2)     * ldb + n);
                r1 = *(const float4*)(B + (long long)(k0 + 2 * k2 + 1) * ldb + n);
            }
            const float* p0 = &r0.x;
            const float* p1 = &r1.x;
#pragma unroll
            for (int j = 0; j < 4; j++) {
                unsigned h, lo;
                split2(p0[j], p1[j], h, lo);
                BsHi[k2][f4n * 4 + j] = h;
                BsLo[k2][f4n * 4 + j] = lo;
            }
        }
        __syncthreads();

        // ---- fragments + 3 mma passes
        unsigned ah[4][4];
#pragma unroll
        for (int mt = 0; mt < 4; mt++) {
            int mr = wm * 64 + mt * 16;
            ah[mt][0] = AsHi[tg    ][mr + g    ];
            ah[mt][1] = AsHi[tg    ][mr + g + 8];
            ah[mt][2] = AsHi[tg + 4][mr + g    ];
            ah[mt][3] = AsHi[tg + 4][mr + g + 8];
        }
        unsigned bh[4][2];
#pragma unroll
        for (int nt = 0; nt < 4; nt++) {
            int nc = wn * 32 + nt * 8 + g;
            bh[nt][0] = BsHi[tg    ][nc];
            bh[nt][1] = BsHi[tg + 4][nc];
        }
        // hi * hi
#pragma unroll
        for (int mt = 0; mt < 4; mt++)
#pragma unroll
            for (int nt = 0; nt < 4; nt++)
                mma16816(acc[mt][nt], ah[mt], bh[nt]);
        // lo * hi
        {
            unsigned al[4][4];
#pragma unroll
            for (int mt = 0; mt < 4; mt++) {
                int mr = wm * 64 + mt * 16;
                al[mt][0] = AsLo[tg    ][mr + g    ];
                al[mt][1] = AsLo[tg    ][mr + g + 8];
                al[mt][2] = AsLo[tg + 4][mr + g    ];
                al[mt][3] = AsLo[tg + 4][mr + g + 8];
            }
#pragma unroll
            for (int mt = 0; mt < 4; mt++)
#pragma unroll
                for (int nt = 0; nt < 4; nt++)
                    mma16816(acc[mt][nt], al[mt], bh[nt]);
        }
        // hi * lo
        {
            unsigned bl[4][2];
#pragma unroll
            for (int nt = 0; nt < 4; nt++) {
                int nc = wn * 32 + nt * 8 + g;
                bl[nt][0] = BsLo[tg    ][nc];
                bl[nt][1] = BsLo[tg + 4][nc];
            }
#pragma unroll
            for (int mt = 0; mt < 4; mt++)
#pragma unroll
                for (int nt = 0; nt < 4; nt++)
                    mma16816(acc[mt][nt], ah[mt], bl[nt]);
        }
        __syncthreads();
    }

    // ---- epilogue
#pragma unroll
    for (int mt = 0; mt < 4; mt++) {
        int m1 = m0 + wm * 64 + mt * 16 + g;
        int m2 = m1 + 8;
#pragma unroll
        for (int nt = 0; nt < 4; nt++) {
            int n1 = n0 + wn * 32 + nt * 8 + 2 * tg;
            float b0v = 0.f, b1v = 0.f;
            if (bias) {
                if (n1     < N) b0v = bias[n1];
                if (n1 + 1 < N) b1v = bias[n1 + 1];
            }
            const float* c = acc[mt][nt];
            if (m1 < M) {
                if (n1     < N) C[(long long)m1 * ldc + n1    ] = c[0] * alpha + b0v;
                if (n1 + 1 < N) C[(long long)m1 * ldc + n1 + 1] = c[1] * alpha + b1v;
            }
            if (m2 < M) {
                if (n1     < N) C[(long long)m2 * ldc + n1    ] = c[2] * alpha + b0v;
                if (n1 + 1 < N) C[(long long)m2 * ldc + n1 + 1] = c[3] * alpha + b1v;
            }
        }
    }
}

// ============== fp32 tiled SGEMM (kept for the decision MLP path) ============
__global__ __launch_bounds__(256)
void sgemm_kernel(const float* __restrict__ A, const float* __restrict__ B,
                  const float* __restrict__ bias, float* __restrict__ C,
                  int M, int N, int K,
                  int aRow, int bN, int bK, int ldc,
                  int innerCount,
                  long long aOuter, long long aInner,
                  long long bOuter, long long bInner,
                  long long cOuter, long long cInner,
                  float alpha, int act)
{
    int z  = blockIdx.z;
    int zo = z / innerCount, zi = z % innerCount;
    A += (long long)zo * aOuter + (long long)zi * aInner;
    B += (long long)zo * bOuter + (long long)zi * bInner;
    C += (long long)zo * cOuter + (long long)zi * cInner;

    __shared__ float As[16][64];
    __shared__ float Bs[16][64];

    const int t  = threadIdx.x;
    const int ty = t >> 4;
    const int tx = t & 15;
    const int m0 = blockIdx.y * 64;
    const int n0 = blockIdx.x * 64;

    const int rl = t >> 2;
    const int kl = (t & 3) * 4;

    float acc[4][4];
#pragma unroll
    for (int i = 0; i < 4; i++)
#pragma unroll
        for (int j = 0; j < 4; j++) acc[i][j] = 0.0f;

    for (int k0 = 0; k0 < K; k0 += 16) {
        {
            const float4 av = *(const float4*)(A + (long long)(m0 + rl) * aRow + k0 + kl);
            As[kl + 0][rl] = av.x;
            As[kl + 1][rl] = av.y;
            As[kl + 2][rl] = av.z;
            As[kl + 3][rl] = av.w;
        }
        if (bK == 1) {
            const float4 bv = *(const float4*)(B + (long long)(n0 + rl) * bN + k0 + kl);
            Bs[kl + 0][rl] = bv.x;
            Bs[kl + 1][rl] = bv.y;
            Bs[kl + 2][rl] = bv.z;
            Bs[kl + 3][rl] = bv.w;
        } else {
#pragma unroll
            for (int l = 0; l < 4; l++) {
                int idx = t + l * 256;
                int kk = idx >> 6;
                int nn = idx & 63;
                Bs[kk][nn] = B[(long long)(k0 + kk) * bK + (n0 + nn)];
            }
        }
        __syncthreads();

#pragma unroll
        for (int kk = 0; kk < 16; kk++) {
            const float4 a4 = *(const float4*)(&As[kk][ty * 4]);
            const float4 b4 = *(const float4*)(&Bs[kk][tx * 4]);
            float a[4] = {a4.x, a4.y, a4.z, a4.w};
            float b[4] = {b4.x, b4.y, b4.z, b4.w};
#pragma unroll
            for (int i = 0; i < 4; i++)
#pragma unroll
                for (int j = 0; j < 4; j++) acc[i][j] += a[i] * b[j];
        }
        __syncthreads();
    }

    float bv[4] = {0.f, 0.f, 0.f, 0.f};
    if (bias) {
#pragma unroll
        for (int j = 0; j < 4; j++) bv[j] = bias[n0 + tx * 4 + j];
    }
#pragma unroll
    for (int i = 0; i < 4; i++) {
        int m = m0 + ty * 4 + i;
        if (m < M) {
#pragma unroll
            for (int j = 0; j < 4; j++) {
                int n = n0 + tx * 4 + j;
                float v = acc[i][j] * alpha + bv[j];
                if (act == 1) v = gelu_exact(v);
                C[(long long)m * ldc + n] = v;
            }
        }
    }
}

// ---------------- tgt_rep: masked mean over 64 template tokens ---------------
__global__ void tgt_kernel(const float* __restrict__ x, const float* __restrict__ mask)
{
    __shared__ float sm[TTOK];
    int b = blockIdx.x;
    if (threadIdx.x < TTOK) sm[threadIdx.x] = mask[b * TTOK + threadIdx.x];
    __syncthreads();
    for (int c = threadIdx.x; c < CDIM; c += blockDim.x) {
        float s = 0.0f;
        const float* xb = x + (long long)b * NTOK * CDIM + c;
#pragma unroll 8
        for (int t = 0; t < TTOK; t++) s += xb[(long long)t * CDIM] * sm[t];
        g_tgt[b * CDIM + c] = s * (1.0f / (float)TTOK);
    }
}

// ---------------- build MLP input: [x_search | tgt_rep] ----------------------
__global__ void minprep_kernel(const float* __restrict__ x)
{
    long long idx = (long long)blockIdx.x * blockDim.x + threadIdx.x;
    const long long total = (long long)BSZ * STOK * 2 * CDIM;
    if (idx >= total) return;
    int c   = (int)(idx % (2 * CDIM));
    int tok = (int)(idx / (2 * CDIM));
    int b = tok / STOK, s = tok % STOK;
    float v;
    if (c < CDIM) v = x[((long long)b * NTOK + (TTOK + s)) * CDIM + c];
    else          v = g_tgt[b * CDIM + (c - CDIM)];
    g_min[idx] = v;
}

// ---------------- final MLP layer + argmax + groups + decision out -----------
__global__ void decide_kernel(const float* __restrict__ dp3_w,
                              const float* __restrict__ dp3_b,
                              float* dec_out)
{
    int idx = blockIdx.x * blockDim.x + threadIdx.x;
    if (idx >= BSZ * NTOK) return;
    int b = idx / NTOK, tok = idx % NTOK;
    if (tok < TTOK) { g_grp[idx] = 0; return; }
    int s = tok - TTOK;
    const float* h = g_h2 + ((long long)b * STOK + s) * 192;
    float l0 = dp3_b[0], l1 = dp3_b[1];
#pragma unroll 4
    for (int k = 0; k < 192; k++) {
        float hv = h[k];
        l0 += hv * dp3_w[k];
        l1 += hv * dp3_w[192 + k];
    }
    int cls = (l1 > l0) ? 1 : 0;
    g_grp[idx] = 1 + cls;
    if (dec_out) {
        long long o = ((long long)b * STOK + s) * 2;
        dec_out[o + 0] = (cls == 0) ? 1.0f : 0.0f;
        dec_out[o + 1] = (cls == 1) ? 1.0f : 0.0f;
    }
}

// ---------------- policy softmax (in-place on g_S), one warp per row ---------
__global__ void softmax_policy_kernel()
{
    const int warp = threadIdx.x >> 5;
    const int lane = threadIdx.x & 31;
    const long long r = (long long)blockIdx.x * 4 + warp;
    const long long nrows = (long long)BSZ * HN * NTOK;
    if (r >= nrows) return;
    int bh = (int)(r / NTOK);
    int i  = (int)(r % NTOK);
    int b  = bh / HN;
    float* row = g_S + (long long)bh * NTOK * NTOK + (long long)i * NTOK;
    const int* grp = g_grp + b * NTOK;
    int gi = grp[i];

    float sv[10];
    float mx = -3.4e38f;
#pragma unroll
    for (int l = 0; l < 10; l++) {
        sv[l] = row[lane + l * 32];
        mx = fmaxf(mx, sv[l]);
    }
#pragma unroll
    for (int o = 16; o > 0; o >>= 1) mx = fmaxf(mx, __shfl_xor_sync(0xffffffffu, mx, o));

    float sum = 0.0f;
#pragma unroll
    for (int l = 0; l < 10; l++) {
        int j = lane + l * 32;
        int gj = grp[j];
        float m = (gi == 2 || gj == 2 || gi == gj) ? 1.0f : 0.0f;
        float e = expf(sv[l] - mx) * m;
        sv[l] = e;
        sum += e;
    }
#pragma unroll
    for (int o = 16; o > 0; o >>= 1) sum += __shfl_xor_sync(0xffffffffu, sum, o);

    const float epsn = 1e-6f / (float)NTOK;
    float inv = 1.0f / (sum + 1e-6f);
#pragma unroll
    for (int l = 0; l < 10; l++) row[lane + l * 32] = (sv[l] + epsn) * inv;
}

// ---------------- host launcher ----------------------------------------------
extern "C" void kernel_launch(void* const* d_in, const int* in_sizes, int n_in,
                              void* d_out, int out_size)
{
    const float* x      = (const float*)d_in[0];
    const float* tmask  = (const float*)d_in[1];
    const float* qkv_w  = (const float*)d_in[2];
    const float* qkv_b  = (const float*)d_in[3];
    const float* proj_w = (const float*)d_in[4];
    const float* proj_b = (const float*)d_in[5];
    const float* dp1_w  = (const float*)d_in[6];
    const float* dp1_b  = (const float*)d_in[7];
    const float* dp2_w  = (const float*)d_in[8];
    const float* dp2_b  = (const float*)d_in[9];
    const float* dp3_w  = (const float*)d_in[10];
    const float* dp3_b  = (const float*)d_in[11];
    float* out = (float*)d_out;

    const long long OUT_MAIN = (long long)BSZ * NTOK * CDIM;
    const long long OUT_DEC  = (long long)BSZ * STOK * 2;
    float* dec_out = ((long long)out_size >= OUT_MAIN + OUT_DEC) ? (out + OUT_MAIN) : nullptr;

    float *p_tgt, *p_min, *p_h1, *p_h2, *p_qkv, *p_S, *p_ao;
    cudaGetSymbolAddress((void**)&p_tgt, g_tgt);
    cudaGetSymbolAddress((void**)&p_min, g_min);
    cudaGetSymbolAddress((void**)&p_h1,  g_h1);
    cudaGetSymbolAddress((void**)&p_h2,  g_h2);
    cudaGetSymbolAddress((void**)&p_qkv, g_qkv);
    cudaGetSymbolAddress((void**)&p_S,   g_S);
    cudaGetSymbolAddress((void**)&p_ao,  g_ao);

    // 1) tgt representation
    tgt_kernel<<<BSZ, 256>>>(x, tmask);

    // 2) MLP input concat
    {
        long long total = (long long)BSZ * STOK * 2 * CDIM;
        int blocks = (int)((total + 255) / 256);
        minprep_kernel<<<blocks, 256>>>(x);
    }

    // 3) QKV GEMM (bf16x3 tensor): [10240,768] x [2304,768]^T -> [10240,2304]
    mma_gemm_kernel<<<dim3(2304 / 128, (BSZ * NTOK) / 128, 1), 256>>>(
        x, qkv_w, qkv_b, p_qkv,
        BSZ * NTOK, 3 * CDIM, CDIM,
        CDIM, CDIM, 3 * CDIM,
        0, 1, 0, 0, 0, 0, 0, 0, 1.0f);

    // 4) MLP layer1 (fp32, decision path — unchanged)
    sgemm_kernel<<<dim3(384 / 64, (BSZ * STOK) / 64, 1), 256>>>(
        p_min, dp1_w, dp1_b, p_h1,
        BSZ * STOK, 384, 2 * CDIM,
        2 * CDIM, 2 * CDIM, 1, 384,
        1, 0, 0, 0, 0, 0, 0, 1.0f, 1);

    // 5) MLP layer2 (fp32, decision path — unchanged)
    sgemm_kernel<<<dim3(192 / 64, (BSZ * STOK) / 64, 1), 256>>>(
        p_h1, dp2_w, dp2_b, p_h2,
        BSZ * STOK, 192, 384,
        384, 384, 1, 192,
        1, 0, 0, 0, 0, 0, 0, 1.0f, 1);

    // 6) decision + groups
    decide_kernel<<<(BSZ * NTOK + 255) / 256, 256>>>(dp3_w, dp3_b, dec_out);

    // 7) S = Q K^T * scale (bf16x3 tensor), batched over (b,h)
    {
        long long aOuter = (long long)NTOK * 3 * CDIM;
        long long strS   = (long long)NTOK * NTOK;
        mma_gemm_kernel<<<dim3(3, 3, BSZ * HN), 256>>>(
            p_qkv, p_qkv + CDIM, nullptr, p_S,
            NTOK, NTOK, HD,
            3 * CDIM, 3 * CDIM, NTOK,
            0, HN,
            aOuter, HD,
            aOuter, HD,
            (long long)HN * strS, strS,
            0.125f);
    }

    // 8) policy softmax
    {
        long long nrows = (long long)BSZ * HN * NTOK;
        int blocks = (int)((nrows + 3) / 4);
        softmax_policy_kernel<<<blocks, 128>>>();
    }

    // 9) O = P V (bf16x3 tensor), batched over (b,h); B mode 1 (V is [k][n])
    {
        long long strS = (long long)NTOK * NTOK;
        mma_gemm_kernel<<<dim3(1, 3, BSZ * HN), 256>>>(
            p_S, p_qkv + 2 * CDIM, nullptr, p_ao,
            NTOK, HD, NTOK,
            NTOK, 3 * CDIM, CDIM,
            1, HN,
            (long long)HN * strS, strS,
            (long long)NTOK * 3 * CDIM, HD,
            (long long)NTOK * CDIM, HD,
            1.0f);
    }

    // 10) output projection (bf16x3 tensor): [10240,768] x [768,768]^T + bias
    mma_gemm_kernel<<<dim3(CDIM / 128, (BSZ * NTOK) / 128, 1), 256>>>(
        p_ao, proj_w, proj_b, out,
        BSZ * NTOK, CDIM, CDIM,
        CDIM, CDIM, CDIM,
        0, 1, 0, 0, 0, 0, 0, 0, 1.0f);
}

// round 3
// speedup vs baseline: 1.6278x; 1.0430x over previous
#include <cuda_runtime.h>
#include <cuda_bf16.h>
#include <math.h>

// Problem constants
#define BSZ  32
#define NTOK 320
#define CDIM 768
#define HN   12
#define STOK 256
#define TTOK 64
#define HD   64

// ---------------- scratch (__device__ globals: allocation-free) --------------
__device__ float g_tgt[BSZ * CDIM];                      // [B,C]
__device__ float g_min[BSZ * STOK * 2 * CDIM];           // [B*S, 1536]
__device__ float g_h1 [BSZ * STOK * 384];                // [B*S, 384]
__device__ float g_h2 [BSZ * STOK * 192];                // [B*S, 192]
__device__ int   g_grp[BSZ * NTOK];                      // token group 0/1/2
__device__ float g_qkv[BSZ * NTOK * 3 * CDIM];           // [B*N, 2304]
__device__ float g_S  [(size_t)BSZ * HN * NTOK * NTOK];  // [B*H, 320, 320]
__device__ float g_ao [BSZ * NTOK * CDIM];               // attn out pre-proj

__device__ __forceinline__ float gelu_exact(float v) {
    return 0.5f * v * (1.0f + erff(v * 0.70710678118654752f));
}

// ================= bf16x3 split-precision tensor-core GEMM ===================
__device__ __forceinline__ void split2(float x0, float x1, unsigned& hi, unsigned& lo) {
    __nv_bfloat16 h0 = __float2bfloat16(x0);
    __nv_bfloat16 h1 = __float2bfloat16(x1);
    float r0 = x0 - __bfloat162float(h0);
    float r1 = x1 - __bfloat162float(h1);
    __nv_bfloat16 l0 = __float2bfloat16(r0);
    __nv_bfloat16 l1 = __float2bfloat16(r1);
    hi = (unsigned)__bfloat16_as_ushort(h0) | ((unsigned)__bfloat16_as_ushort(h1) << 16);
    lo = (unsigned)__bfloat16_as_ushort(l0) | ((unsigned)__bfloat16_as_ushort(l1) << 16);
}

__device__ __forceinline__ void mma16816(float* c, const unsigned* a, const unsigned* b) {
    asm volatile(
        "mma.sync.aligned.m16n8k16.row.col.f32.bf16.bf16.f32 "
        "{%0,%1,%2,%3}, {%4,%5,%6,%7}, {%8,%9}, {%0,%1,%2,%3};\n"
        : "+f"(c[0]), "+f"(c[1]), "+f"(c[2]), "+f"(c[3])
        : "r"(a[0]), "r"(a[1]), "r"(a[2]), "r"(a[3]), "r"(b[0]), "r"(b[1]));
}

#define SPAD 132   // 128 + 4 padding (uint32 lanes)

__global__ __launch_bounds__(256, 2)
void mma_gemm_kernel(const float* __restrict__ A, const float* __restrict__ B,
                     const float* __restrict__ bias, float* __restrict__ C,
                     int M, int N, int K, int lda, int ldb, int ldc,
                     int bMode, int innerCount,
                     long long aOuter, long long aInner,
                     long long bOuter, long long bInner,
                     long long cOuter, long long cInner,
                     float alpha)
{
    int z  = blockIdx.z;
    int zo = z / innerCount, zi = z % innerCount;
    A += (long long)zo * aOuter + (long long)zi * aInner;
    B += (long long)zo * bOuter + (long long)zi * bInner;
    C += (long long)zo * cOuter + (long long)zi * cInner;

    __shared__ unsigned AsHi[8][SPAD], AsLo[8][SPAD];
    __shared__ unsigned BsHi[8][SPAD], BsLo[8][SPAD];

    const int t    = threadIdx.x;
    const int lane = t & 31;
    const int warp = t >> 5;
    const int wm   = warp >> 2;        // 0..1
    const int wn   = warp & 3;         // 0..3
    const int g    = lane >> 2;        // 0..7
    const int tg   = lane & 3;         // 0..3
    const int m0   = blockIdx.y * 128;
    const int n0   = blockIdx.x * 128;

    float acc[4][4][4];
#pragma unroll
    for (int i = 0; i < 4; i++)
#pragma unroll
        for (int j = 0; j < 4; j++)
#pragma unroll
            for (int r = 0; r < 4; r++) acc[i][j][r] = 0.0f;

    for (int k0 = 0; k0 < K; k0 += 16) {
#pragma unroll
        for (int l = 0; l < 2; l++) {
            int it  = t * 2 + l;          // 0..511
            int row = it >> 2;            // 0..127
            int f4  = it & 3;             // 0..3 -> k offset f4*4
            int m   = m0 + row;
            float4 v = make_float4(0.f, 0.f, 0.f, 0.f);
            if (m < M) v = *(const float4*)(A + (long long)m * lda + k0 + f4 * 4);
            unsigned h0, l0, h1, l1;
            split2(v.x, v.y, h0, l0);
            split2(v.z, v.w, h1, l1);
            AsHi[f4 * 2 + 0][row] = h0; AsLo[f4 * 2 + 0][row] = l0;
            AsHi[f4 * 2 + 1][row] = h1; AsLo[f4 * 2 + 1][row] = l1;
        }
        if (bMode == 0) {
#pragma unroll
            for (int l = 0; l < 2; l++) {
                int it  = t * 2 + l;
                int row = it >> 2;
                int f4  = it & 3;
                int n   = n0 + row;
                float4 v = make_float4(0.f, 0.f, 0.f, 0.f);
                if (n < N) v = *(const float4*)(B + (long long)n * ldb + k0 + f4 * 4);
                unsigned h0, l0, h1, l1;
                split2(v.x, v.y, h0, l0);
                split2(v.z, v.w, h1, l1);
                BsHi[f4 * 2 + 0][row] = h0; BsLo[f4 * 2 + 0][row] = l0;
                BsHi[f4 * 2 + 1][row] = h1; BsLo[f4 * 2 + 1][row] = l1;
            }
        } else {
            int k2  = t >> 5;             // 0..7
            int f4n = t & 31;             // 0..31
            int n   = n0 + f4n * 4;
            float4 r0 = make_float4(0.f, 0.f, 0.f, 0.f);
            float4 r1 = make_float4(0.f, 0.f, 0.f, 0.f);
            if (n < N) {
                r0 = *(const float4*)(B + (long long)(k0 + 2 * k2)     * ldb + n);
                r1 = *(const float4*)(B + (long long)(k0 + 2 * k2 + 1) * ldb + n);
            }
            const float* p0 = &r0.x;
            const float* p1 = &r1.x;
#pragma unroll
            for (int j = 0; j < 4; j++) {
                unsigned h, lo;
                split2(p0[j], p1[j], h, lo);
                BsHi[k2][f4n * 4 + j] = h;
                BsLo[k2][f4n * 4 + j] = lo;
            }
        }
        __syncthreads();

        unsigned ah[4][4];
#pragma unroll
        for (int mt = 0; mt < 4; mt++) {
            int mr = wm * 64 + mt * 16;
            ah[mt][0] = AsHi[tg    ][mr + g    ];
            ah[mt][1] = AsHi[tg    ][mr + g + 8];
            ah[mt][2] = AsHi[tg + 4][mr + g    ];
            ah[mt][3] = AsHi[tg + 4][mr + g + 8];
        }
        unsigned bh[4][2];
#pragma unroll
        for (int nt = 0; nt < 4; nt++) {
            int nc = wn * 32 + nt * 8 + g;
            bh[nt][0] = BsHi[tg    ][nc];
            bh[nt][1] = BsHi[tg + 4][nc];
        }
#pragma unroll
        for (int mt = 0; mt < 4; mt++)
#pragma unroll
            for (int nt = 0; nt < 4; nt++)
                mma16816(acc[mt][nt], ah[mt], bh[nt]);
        {
            unsigned al[4][4];
#pragma unroll
            for (int mt = 0; mt < 4; mt++) {
                int mr = wm * 64 + mt * 16;
                al[mt][0] = AsLo[tg    ][mr + g    ];
                al[mt][1] = AsLo[tg    ][mr + g + 8];
                al[mt][2] = AsLo[tg + 4][mr + g    ];
                al[mt][3] = AsLo[tg + 4][mr + g + 8];
            }
#pragma unroll
            for (int mt = 0; mt < 4; mt++)
#pragma unroll
                for (int nt = 0; nt < 4; nt++)
                    mma16816(acc[mt][nt], al[mt], bh[nt]);
        }
        {
            unsigned bl[4][2];
#pragma unroll
            for (int nt = 0; nt < 4; nt++) {
                int nc = wn * 32 + nt * 8 + g;
                bl[nt][0] = BsLo[tg    ][nc];
                bl[nt][1] = BsLo[tg + 4][nc];
            }
#pragma unroll
            for (int mt = 0; mt < 4; mt++)
#pragma unroll
                for (int nt = 0; nt < 4; nt++)
                    mma16816(acc[mt][nt], ah[mt], bl[nt]);
        }
        __syncthreads();
    }

#pragma unroll
    for (int mt = 0; mt < 4; mt++) {
        int m1 = m0 + wm * 64 + mt * 16 + g;
        int m2 = m1 + 8;
#pragma unroll
        for (int nt = 0; nt < 4; nt++) {
            int n1 = n0 + wn * 32 + nt * 8 + 2 * tg;
            float b0v = 0.f, b1v = 0.f;
            if (bias) {
                if (n1     < N) b0v = bias[n1];
                if (n1 + 1 < N) b1v = bias[n1 + 1];
            }
            const float* c = acc[mt][nt];
            if (m1 < M) {
                if (n1     < N) C[(long long)m1 * ldc + n1    ] = c[0] * alpha + b0v;
                if (n1 + 1 < N) C[(long long)m1 * ldc + n1 + 1] = c[1] * alpha + b1v;
            }
            if (m2 < M) {
                if (n1     < N) C[(long long)m2 * ldc + n1    ] = c[2] * alpha + b0v;
                if (n1 + 1 < N) C[(long long)m2 * ldc + n1 + 1] = c[3] * alpha + b1v;
            }
        }
    }
}

// ================= tf32x3 tensor GEMM (fp32-equivalent, decision path) =======
// C = A[M,K] * B[N,K]^T + bias, optional exact-GELU. B is [n][k], k contiguous.
__device__ __forceinline__ unsigned f2tf32(float x) {
    unsigned r;
    asm("cvt.rna.tf32.f32 %0, %1;" : "=r"(r) : "f"(x));
    return r;
}
__device__ __forceinline__ void split_tf32(float x, unsigned& hi, unsigned& lo) {
    hi = f2tf32(x);
    lo = f2tf32(x - __uint_as_float(hi));
}
__device__ __forceinline__ void mma1688_tf32(float* c, const unsigned* a, const unsigned* b) {
    asm volatile(
        "mma.sync.aligned.m16n8k8.row.col.f32.tf32.tf32.f32 "
        "{%0,%1,%2,%3}, {%4,%5,%6,%7}, {%8,%9}, {%0,%1,%2,%3};\n"
        : "+f"(c[0]), "+f"(c[1]), "+f"(c[2]), "+f"(c[3])
        : "r"(a[0]), "r"(a[1]), "r"(a[2]), "r"(a[3]), "r"(b[0]), "r"(b[1]));
}

__global__ __launch_bounds__(256, 2)
void mma_tf32_kernel(const float* __restrict__ A, const float* __restrict__ B,
                     const float* __restrict__ bias, float* __restrict__ C,
                     int M, int N, int K, int lda, int ldb, int ldc, int act)
{
    __shared__ unsigned AsHi[16][SPAD], AsLo[16][SPAD];
    __shared__ unsigned BsHi[16][SPAD], BsLo[16][SPAD];

    const int t    = threadIdx.x;
    const int lane = t & 31;
    const int warp = t >> 5;
    const int wm   = warp >> 2;        // 0..1
    const int wn   = warp & 3;         // 0..3
    const int g    = lane >> 2;        // 0..7
    const int tg   = lane & 3;         // 0..3
    const int m0   = blockIdx.y * 128;
    const int n0   = blockIdx.x * 128;

    float acc[4][4][4];
#pragma unroll
    for (int i = 0; i < 4; i++)
#pragma unroll
        for (int j = 0; j < 4; j++)
#pragma unroll
            for (int r = 0; r < 4; r++) acc[i][j][r] = 0.0f;

    for (int k0 = 0; k0 < K; k0 += 16) {
        // A slab: 128 rows x 16 k, 512 float4 loads over 256 threads
#pragma unroll
        for (int l = 0; l < 2; l++) {
            int it  = t * 2 + l;
            int row = it >> 2;
            int f4  = it & 3;
            int m   = m0 + row;
            float4 v = make_float4(0.f, 0.f, 0.f, 0.f);
            if (m < M) v = *(const float4*)(A + (long long)m * lda + k0 + f4 * 4);
            const float* p = &v.x;
#pragma unroll
            for (int j = 0; j < 4; j++) {
                unsigned h, lo;
                split_tf32(p[j], h, lo);
                AsHi[f4 * 4 + j][row] = h;
                AsLo[f4 * 4 + j][row] = lo;
            }
        }
        // B slab: [n][k]
#pragma unroll
        for (int l = 0; l < 2; l++) {
            int it  = t * 2 + l;
            int row = it >> 2;
            int f4  = it & 3;
            int n   = n0 + row;
            float4 v = make_float4(0.f, 0.f, 0.f, 0.f);
            if (n < N) v = *(const float4*)(B + (long long)n * ldb + k0 + f4 * 4);
            const float* p = &v.x;
#pragma unroll
            for (int j = 0; j < 4; j++) {
                unsigned h, lo;
                split_tf32(p[j], h, lo);
                BsHi[f4 * 4 + j][row] = h;
                BsLo[f4 * 4 + j][row] = lo;
            }
        }
        __syncthreads();

#pragma unroll
        for (int ks = 0; ks < 2; ks++) {
            const int kb = ks * 8;
            unsigned ah[4][4], al[4][4];
#pragma unroll
            for (int mt = 0; mt < 4; mt++) {
                int mr = wm * 64 + mt * 16;
                ah[mt][0] = AsHi[kb + tg    ][mr + g    ];
                ah[mt][1] = AsHi[kb + tg    ][mr + g + 8];
                ah[mt][2] = AsHi[kb + tg + 4][mr + g    ];
                ah[mt][3] = AsHi[kb + tg + 4][mr + g + 8];
                al[mt][0] = AsLo[kb + tg    ][mr + g    ];
                al[mt][1] = AsLo[kb + tg    ][mr + g + 8];
                al[mt][2] = AsLo[kb + tg + 4][mr + g    ];
                al[mt][3] = AsLo[kb + tg + 4][mr + g + 8];
            }
            unsigned bh[4][2], bl[4][2];
#pragma unroll
            for (int nt = 0; nt < 4; nt++) {
                int nc = wn * 32 + nt * 8 + g;
                bh[nt][0] = BsHi[kb + tg    ][nc];
                bh[nt][1] = BsHi[kb + tg + 4][nc];
                bl[nt][0] = BsLo[kb + tg    ][nc];
                bl[nt][1] = BsLo[kb + tg + 4][nc];
            }
#pragma unroll
            for (int mt = 0; mt < 4; mt++)
#pragma unroll
                for (int nt = 0; nt < 4; nt++) {
                    mma1688_tf32(acc[mt][nt], ah[mt], bh[nt]);
                    mma1688_tf32(acc[mt][nt], al[mt], bh[nt]);
                    mma1688_tf32(acc[mt][nt], ah[mt], bl[nt]);
                }
        }
        __syncthreads();
    }

#pragma unroll
    for (int mt = 0; mt < 4; mt++) {
        int m1 = m0 + wm * 64 + mt * 16 + g;
        int m2 = m1 + 8;
#pragma unroll
        for (int nt = 0; nt < 4; nt++) {
            int n1 = n0 + wn * 32 + nt * 8 + 2 * tg;
            float b0v = 0.f, b1v = 0.f;
            if (bias) {
                if (n1     < N) b0v = bias[n1];
                if (n1 + 1 < N) b1v = bias[n1 + 1];
            }
            const float* c = acc[mt][nt];
            float v0, v1;
            if (m1 < M) {
                v0 = c[0] + b0v; v1 = c[1] + b1v;
                if (act == 1) { v0 = gelu_exact(v0); v1 = gelu_exact(v1); }
                if (n1     < N) C[(long long)m1 * ldc + n1    ] = v0;
                if (n1 + 1 < N) C[(long long)m1 * ldc + n1 + 1] = v1;
            }
            if (m2 < M) {
                v0 = c[2] + b0v; v1 = c[3] + b1v;
                if (act == 1) { v0 = gelu_exact(v0); v1 = gelu_exact(v1); }
                if (n1     < N) C[(long long)m2 * ldc + n1    ] = v0;
                if (n1 + 1 < N) C[(long long)m2 * ldc + n1 + 1] = v1;
            }
        }
    }
}

// ---------------- tgt_rep: masked mean over 64 template tokens ---------------
__global__ void tgt_kernel(const float* __restrict__ x, const float* __restrict__ mask)
{
    __shared__ float sm[TTOK];
    int b = blockIdx.x;
    if (threadIdx.x < TTOK) sm[threadIdx.x] = mask[b * TTOK + threadIdx.x];
    __syncthreads();
    for (int c = threadIdx.x; c < CDIM; c += blockDim.x) {
        float s = 0.0f;
        const float* xb = x + (long long)b * NTOK * CDIM + c;
#pragma unroll 8
        for (int t = 0; t < TTOK; t++) s += xb[(long long)t * CDIM] * sm[t];
        g_tgt[b * CDIM + c] = s * (1.0f / (float)TTOK);
    }
}

// ---------------- build MLP input: [x_search | tgt_rep] ----------------------
__global__ void minprep_kernel(const float* __restrict__ x)
{
    long long idx = (long long)blockIdx.x * blockDim.x + threadIdx.x;
    const long long total = (long long)BSZ * STOK * 2 * CDIM;
    if (idx >= total) return;
    int c   = (int)(idx % (2 * CDIM));
    int tok = (int)(idx / (2 * CDIM));
    int b = tok / STOK, s = tok % STOK;
    float v;
    if (c < CDIM) v = x[((long long)b * NTOK + (TTOK + s)) * CDIM + c];
    else          v = g_tgt[b * CDIM + (c - CDIM)];
    g_min[idx] = v;
}

// ---------------- final MLP layer + argmax + groups + decision out -----------
__global__ void decide_kernel(const float* __restrict__ dp3_w,
                              const float* __restrict__ dp3_b,
                              float* dec_out)
{
    int idx = blockIdx.x * blockDim.x + threadIdx.x;
    if (idx >= BSZ * NTOK) return;
    int b = idx / NTOK, tok = idx % NTOK;
    if (tok < TTOK) { g_grp[idx] = 0; return; }
    int s = tok - TTOK;
    const float* h = g_h2 + ((long long)b * STOK + s) * 192;
    float l0 = dp3_b[0], l1 = dp3_b[1];
#pragma unroll 4
    for (int k = 0; k < 192; k++) {
        float hv = h[k];
        l0 += hv * dp3_w[k];
        l1 += hv * dp3_w[192 + k];
    }
    int cls = (l1 > l0) ? 1 : 0;
    g_grp[idx] = 1 + cls;
    if (dec_out) {
        long long o = ((long long)b * STOK + s) * 2;
        dec_out[o + 0] = (cls == 0) ? 1.0f : 0.0f;
        dec_out[o + 1] = (cls == 1) ? 1.0f : 0.0f;
    }
}

// ---------------- policy softmax (in-place on g_S), one warp per row ---------
__global__ void softmax_policy_kernel()
{
    const int warp = threadIdx.x >> 5;
    const int lane = threadIdx.x & 31;
    const long long r = (long long)blockIdx.x * 4 + warp;
    const long long nrows = (long long)BSZ * HN * NTOK;
    if (r >= nrows) return;
    int bh = (int)(r / NTOK);
    int i  = (int)(r % NTOK);
    int b  = bh / HN;
    float* row = g_S + (long long)bh * NTOK * NTOK + (long long)i * NTOK;
    const int* grp = g_grp + b * NTOK;
    int gi = grp[i];

    float sv[10];
    float mx = -3.4e38f;
#pragma unroll
    for (int l = 0; l < 10; l++) {
        sv[l] = row[lane + l * 32];
        mx = fmaxf(mx, sv[l]);
    }
#pragma unroll
    for (int o = 16; o > 0; o >>= 1) mx = fmaxf(mx, __shfl_xor_sync(0xffffffffu, mx, o));

    float sum = 0.0f;
#pragma unroll
    for (int l = 0; l < 10; l++) {
        int j = lane + l * 32;
        int gj = grp[j];
        float m = (gi == 2 || gj == 2 || gi == gj) ? 1.0f : 0.0f;
        float e = expf(sv[l] - mx) * m;
        sv[l] = e;
        sum += e;
    }
#pragma unroll
    for (int o = 16; o > 0; o >>= 1) sum += __shfl_xor_sync(0xffffffffu, sum, o);

    const float epsn = 1e-6f / (float)NTOK;
    float inv = 1.0f / (sum + 1e-6f);
#pragma unroll
    for (int l = 0; l < 10; l++) row[lane + l * 32] = (sv[l] + epsn) * inv;
}

// ---------------- host launcher ----------------------------------------------
extern "C" void kernel_launch(void* const* d_in, const int* in_sizes, int n_in,
                              void* d_out, int out_size)
{
    const float* x      = (const float*)d_in[0];
    const float* tmask  = (const float*)d_in[1];
    const float* qkv_w  = (const float*)d_in[2];
    const float* qkv_b  = (const float*)d_in[3];
    const float* proj_w = (const float*)d_in[4];
    const float* proj_b = (const float*)d_in[5];
    const float* dp1_w  = (const float*)d_in[6];
    const float* dp1_b  = (const float*)d_in[7];
    const float* dp2_w  = (const float*)d_in[8];
    const float* dp2_b  = (const float*)d_in[9];
    const float* dp3_w  = (const float*)d_in[10];
    const float* dp3_b  = (const float*)d_in[11];
    float* out = (float*)d_out;

    const long long OUT_MAIN = (long long)BSZ * NTOK * CDIM;
    const long long OUT_DEC  = (long long)BSZ * STOK * 2;
    float* dec_out = ((long long)out_size >= OUT_MAIN + OUT_DEC) ? (out + OUT_MAIN) : nullptr;

    float *p_tgt, *p_min, *p_h1, *p_h2, *p_qkv, *p_S, *p_ao;
    cudaGetSymbolAddress((void**)&p_tgt, g_tgt);
    cudaGetSymbolAddress((void**)&p_min, g_min);
    cudaGetSymbolAddress((void**)&p_h1,  g_h1);
    cudaGetSymbolAddress((void**)&p_h2,  g_h2);
    cudaGetSymbolAddress((void**)&p_qkv, g_qkv);
    cudaGetSymbolAddress((void**)&p_S,   g_S);
    cudaGetSymbolAddress((void**)&p_ao,  g_ao);

    // 1) tgt representation
    tgt_kernel<<<BSZ, 256>>>(x, tmask);

    // 2) MLP input concat
    {
        long long total = (long long)BSZ * STOK * 2 * CDIM;
        int blocks = (int)((total + 255) / 256);
        minprep_kernel<<<blocks, 256>>>(x);
    }

    // 3) QKV GEMM (bf16x3 tensor)
    mma_gemm_kernel<<<dim3(2304 / 128, (BSZ * NTOK) / 128, 1), 256>>>(
        x, qkv_w, qkv_b, p_qkv,
        BSZ * NTOK, 3 * CDIM, CDIM,
        CDIM, CDIM, 3 * CDIM,
        0, 1, 0, 0, 0, 0, 0, 0, 1.0f);

    // 4) MLP layer1 (tf32x3 tensor, fp32-equivalent) + GELU
    mma_tf32_kernel<<<dim3(384 / 128, (BSZ * STOK) / 128, 1), 256>>>(
        p_min, dp1_w, dp1_b, p_h1,
        BSZ * STOK, 384, 2 * CDIM,
        2 * CDIM, 2 * CDIM, 384, 1);

    // 5) MLP layer2 (tf32x3 tensor) + GELU
    mma_tf32_kernel<<<dim3((192 + 127) / 128, (BSZ * STOK) / 128, 1), 256>>>(
        p_h1, dp2_w, dp2_b, p_h2,
        BSZ * STOK, 192, 384,
        384, 384, 192, 1);

    // 6) decision + groups
    decide_kernel<<<(BSZ * NTOK + 255) / 256, 256>>>(dp3_w, dp3_b, dec_out);

    // 7) S = Q K^T * scale (bf16x3 tensor), batched over (b,h)
    {
        long long aOuter = (long long)NTOK * 3 * CDIM;
        long long strS   = (long long)NTOK * NTOK;
        mma_gemm_kernel<<<dim3(3, 3, BSZ * HN), 256>>>(
            p_qkv, p_qkv + CDIM, nullptr, p_S,
            NTOK, NTOK, HD,
            3 * CDIM, 3 * CDIM, NTOK,
            0, HN,
            aOuter, HD,
            aOuter, HD,
            (long long)HN * strS, strS,
            0.125f);
    }

    // 8) policy softmax
    {
        long long nrows = (long long)BSZ * HN * NTOK;
        int blocks = (int)((nrows + 3) / 4);
        softmax_policy_kernel<<<blocks, 128>>>();
    }

    // 9) O = P V (bf16x3 tensor), batched over (b,h)
    {
        long long strS = (long long)NTOK * NTOK;
        mma_gemm_kernel<<<dim3(1, 3, BSZ * HN), 256>>>(
            p_S, p_qkv + 2 * CDIM, nullptr, p_ao,
            NTOK, HD, NTOK,
            NTOK, 3 * CDIM, CDIM,
            1, HN,
            (long long)HN * strS, strS,
            (long long)NTOK * 3 * CDIM, HD,
            (long long)NTOK * CDIM, HD,
            1.0f);
    }

    // 10) output projection (bf16x3 tensor)
    mma_gemm_kernel<<<dim3(CDIM / 128, (BSZ * NTOK) / 128, 1), 256>>>(
        p_ao, proj_w, proj_b, out,
        BSZ * NTOK, CDIM, CDIM,
        CDIM, CDIM, CDIM,
        0, 1, 0, 0, 0, 0, 0, 0, 1.0f);
}

// round 4
// speedup vs baseline: 1.9564x; 1.2018x over previous
#include <cuda_runtime.h>
#include <cuda_bf16.h>
#include <math.h>

// Problem constants
#define BSZ  32
#define NTOK 320
#define CDIM 768
#define HN   12
#define STOK 256
#define TTOK 64
#define HD   64

// ---------------- scratch (__device__ globals: allocation-free) --------------
__device__ float g_tgt [BSZ * CDIM];                     // [B,C]
__device__ float g_tgtb[BSZ * 384];                      // per-batch MLP1 bias
__device__ float g_h1 [BSZ * STOK * 384];                // [B*S, 384]
__device__ float g_h2 [BSZ * STOK * 192];                // [B*S, 192]
__device__ int   g_grp[BSZ * NTOK];                      // token group 0/1/2
__device__ float g_qkv[BSZ * NTOK * 3 * CDIM];           // [B*N, 2304]
__device__ float g_S  [(size_t)BSZ * HN * NTOK * NTOK];  // [B*H, 320, 320]
__device__ float g_ao [BSZ * NTOK * CDIM];               // attn out pre-proj

__device__ __forceinline__ float gelu_exact(float v) {
    return 0.5f * v * (1.0f + erff(v * 0.70710678118654752f));
}

// ================= bf16x3 split-precision tensor-core GEMM ===================
__device__ __forceinline__ void split2(float x0, float x1, unsigned& hi, unsigned& lo) {
    __nv_bfloat16 h0 = __float2bfloat16(x0);
    __nv_bfloat16 h1 = __float2bfloat16(x1);
    float r0 = x0 - __bfloat162float(h0);
    float r1 = x1 - __bfloat162float(h1);
    __nv_bfloat16 l0 = __float2bfloat16(r0);
    __nv_bfloat16 l1 = __float2bfloat16(r1);
    hi = (unsigned)__bfloat16_as_ushort(h0) | ((unsigned)__bfloat16_as_ushort(h1) << 16);
    lo = (unsigned)__bfloat16_as_ushort(l0) | ((unsigned)__bfloat16_as_ushort(l1) << 16);
}

__device__ __forceinline__ void mma16816(float* c, const unsigned* a, const unsigned* b) {
    asm volatile(
        "mma.sync.aligned.m16n8k16.row.col.f32.bf16.bf16.f32 "
        "{%0,%1,%2,%3}, {%4,%5,%6,%7}, {%8,%9}, {%0,%1,%2,%3};\n"
        : "+f"(c[0]), "+f"(c[1]), "+f"(c[2]), "+f"(c[3])
        : "r"(a[0]), "r"(a[1]), "r"(a[2]), "r"(a[3]), "r"(b[0]), "r"(b[1]));
}

#define SPAD 132   // 128 + 4 padding (uint32 lanes)

__global__ __launch_bounds__(256, 2)
void mma_gemm_kernel(const float* __restrict__ A, const float* __restrict__ B,
                     const float* __restrict__ bias, float* __restrict__ C,
                     int M, int N, int K, int lda, int ldb, int ldc,
                     int bMode, int innerCount,
                     long long aOuter, long long aInner,
                     long long bOuter, long long bInner,
                     long long cOuter, long long cInner,
                     float alpha)
{
    int z  = blockIdx.z;
    int zo = z / innerCount, zi = z % innerCount;
    A += (long long)zo * aOuter + (long long)zi * aInner;
    B += (long long)zo * bOuter + (long long)zi * bInner;
    C += (long long)zo * cOuter + (long long)zi * cInner;

    __shared__ unsigned AsHi[8][SPAD], AsLo[8][SPAD];
    __shared__ unsigned BsHi[8][SPAD], BsLo[8][SPAD];

    const int t    = threadIdx.x;
    const int lane = t & 31;
    const int warp = t >> 5;
    const int wm   = warp >> 2;
    const int wn   = warp & 3;
    const int g    = lane >> 2;
    const int tg   = lane & 3;
    const int m0   = blockIdx.y * 128;
    const int n0   = blockIdx.x * 128;

    float acc[4][4][4];
#pragma unroll
    for (int i = 0; i < 4; i++)
#pragma unroll
        for (int j = 0; j < 4; j++)
#pragma unroll
            for (int r = 0; r < 4; r++) acc[i][j][r] = 0.0f;

    for (int k0 = 0; k0 < K; k0 += 16) {
#pragma unroll
        for (int l = 0; l < 2; l++) {
            int it  = t * 2 + l;
            int row = it >> 2;
            int f4  = it & 3;
            int m   = m0 + row;
            float4 v = make_float4(0.f, 0.f, 0.f, 0.f);
            if (m < M) v = *(const float4*)(A + (long long)m * lda + k0 + f4 * 4);
            unsigned h0, l0, h1, l1;
            split2(v.x, v.y, h0, l0);
            split2(v.z, v.w, h1, l1);
            AsHi[f4 * 2 + 0][row] = h0; AsLo[f4 * 2 + 0][row] = l0;
            AsHi[f4 * 2 + 1][row] = h1; AsLo[f4 * 2 + 1][row] = l1;
        }
        if (bMode == 0) {
#pragma unroll
            for (int l = 0; l < 2; l++) {
                int it  = t * 2 + l;
                int row = it >> 2;
                int f4  = it & 3;
                int n   = n0 + row;
                float4 v = make_float4(0.f, 0.f, 0.f, 0.f);
                if (n < N) v = *(const float4*)(B + (long long)n * ldb + k0 + f4 * 4);
                unsigned h0, l0, h1, l1;
                split2(v.x, v.y, h0, l0);
                split2(v.z, v.w, h1, l1);
                BsHi[f4 * 2 + 0][row] = h0; BsLo[f4 * 2 + 0][row] = l0;
                BsHi[f4 * 2 + 1][row] = h1; BsLo[f4 * 2 + 1][row] = l1;
            }
        } else {
            int k2  = t >> 5;
            int f4n = t & 31;
            int n   = n0 + f4n * 4;
            float4 r0 = make_float4(0.f, 0.f, 0.f, 0.f);
            float4 r1 = make_float4(0.f, 0.f, 0.f, 0.f);
            if (n < N) {
                r0 = *(const float4*)(B + (long long)(k0 + 2 * k2)     * ldb + n);
                r1 = *(const float4*)(B + (long long)(k0 + 2 * k2 + 1) * ldb + n);
            }
            const float* p0 = &r0.x;
            const float* p1 = &r1.x;
#pragma unroll
            for (int j = 0; j < 4; j++) {
                unsigned h, lo;
                split2(p0[j], p1[j], h, lo);
                BsHi[k2][f4n * 4 + j] = h;
                BsLo[k2][f4n * 4 + j] = lo;
            }
        }
        __syncthreads();

        unsigned ah[4][4];
#pragma unroll
        for (int mt = 0; mt < 4; mt++) {
            int mr = wm * 64 + mt * 16;
            ah[mt][0] = AsHi[tg    ][mr + g    ];
            ah[mt][1] = AsHi[tg    ][mr + g + 8];
            ah[mt][2] = AsHi[tg + 4][mr + g    ];
            ah[mt][3] = AsHi[tg + 4][mr + g + 8];
        }
        unsigned bh[4][2];
#pragma unroll
        for (int nt = 0; nt < 4; nt++) {
            int nc = wn * 32 + nt * 8 + g;
            bh[nt][0] = BsHi[tg    ][nc];
            bh[nt][1] = BsHi[tg + 4][nc];
        }
#pragma unroll
        for (int mt = 0; mt < 4; mt++)
#pragma unroll
            for (int nt = 0; nt < 4; nt++)
                mma16816(acc[mt][nt], ah[mt], bh[nt]);
        {
            unsigned al[4][4];
#pragma unroll
            for (int mt = 0; mt < 4; mt++) {
                int mr = wm * 64 + mt * 16;
                al[mt][0] = AsLo[tg    ][mr + g    ];
                al[mt][1] = AsLo[tg    ][mr + g + 8];
                al[mt][2] = AsLo[tg + 4][mr + g    ];
                al[mt][3] = AsLo[tg + 4][mr + g + 8];
            }
#pragma unroll
            for (int mt = 0; mt < 4; mt++)
#pragma unroll
                for (int nt = 0; nt < 4; nt++)
                    mma16816(acc[mt][nt], al[mt], bh[nt]);
        }
        {
            unsigned bl[4][2];
#pragma unroll
            for (int nt = 0; nt < 4; nt++) {
                int nc = wn * 32 + nt * 8 + g;
                bl[nt][0] = BsLo[tg    ][nc];
                bl[nt][1] = BsLo[tg + 4][nc];
            }
#pragma unroll
            for (int mt = 0; mt < 4; mt++)
#pragma unroll
                for (int nt = 0; nt < 4; nt++)
                    mma16816(acc[mt][nt], ah[mt], bl[nt]);
        }
        __syncthreads();
    }

#pragma unroll
    for (int mt = 0; mt < 4; mt++) {
        int m1 = m0 + wm * 64 + mt * 16 + g;
        int m2 = m1 + 8;
#pragma unroll
        for (int nt = 0; nt < 4; nt++) {
            int n1 = n0 + wn * 32 + nt * 8 + 2 * tg;
            float b0v = 0.f, b1v = 0.f;
            if (bias) {
                if (n1     < N) b0v = bias[n1];
                if (n1 + 1 < N) b1v = bias[n1 + 1];
            }
            const float* c = acc[mt][nt];
            if (m1 < M) {
                if (n1     < N) C[(long long)m1 * ldc + n1    ] = c[0] * alpha + b0v;
                if (n1 + 1 < N) C[(long long)m1 * ldc + n1 + 1] = c[1] * alpha + b1v;
            }
            if (m2 < M) {
                if (n1     < N) C[(long long)m2 * ldc + n1    ] = c[2] * alpha + b0v;
                if (n1 + 1 < N) C[(long long)m2 * ldc + n1 + 1] = c[3] * alpha + b1v;
            }
        }
    }
}

// ================= tf32x3 tensor GEMM (fp32-equivalent, decision path) =======
// C = A[M,K] * B[N,K]^T + bias, optional exact-GELU. Batched over blockIdx.z
// via aBatch/biasBatch/cBatch element strides. B shared across batches.
__device__ __forceinline__ unsigned f2tf32(float x) {
    unsigned r;
    asm("cvt.rna.tf32.f32 %0, %1;" : "=r"(r) : "f"(x));
    return r;
}
__device__ __forceinline__ void split_tf32(float x, unsigned& hi, unsigned& lo) {
    hi = f2tf32(x);
    lo = f2tf32(x - __uint_as_float(hi));
}
__device__ __forceinline__ void mma1688_tf32(float* c, const unsigned* a, const unsigned* b) {
    asm volatile(
        "mma.sync.aligned.m16n8k8.row.col.f32.tf32.tf32.f32 "
        "{%0,%1,%2,%3}, {%4,%5,%6,%7}, {%8,%9}, {%0,%1,%2,%3};\n"
        : "+f"(c[0]), "+f"(c[1]), "+f"(c[2]), "+f"(c[3])
        : "r"(a[0]), "r"(a[1]), "r"(a[2]), "r"(a[3]), "r"(b[0]), "r"(b[1]));
}

__global__ __launch_bounds__(256, 2)
void mma_tf32_kernel(const float* __restrict__ A, const float* __restrict__ B,
                     const float* __restrict__ bias, float* __restrict__ C,
                     int M, int N, int K, int lda, int ldb, int ldc, int act,
                     long long aBatch, long long biasBatch, long long cBatch)
{
    const int z = blockIdx.z;
    A += (long long)z * aBatch;
    C += (long long)z * cBatch;
    if (bias) bias += (long long)z * biasBatch;

    __shared__ unsigned AsHi[16][SPAD], AsLo[16][SPAD];
    __shared__ unsigned BsHi[16][SPAD], BsLo[16][SPAD];

    const int t    = threadIdx.x;
    const int lane = t & 31;
    const int warp = t >> 5;
    const int wm   = warp >> 2;
    const int wn   = warp & 3;
    const int g    = lane >> 2;
    const int tg   = lane & 3;
    const int m0   = blockIdx.y * 128;
    const int n0   = blockIdx.x * 128;

    float acc[4][4][4];
#pragma unroll
    for (int i = 0; i < 4; i++)
#pragma unroll
        for (int j = 0; j < 4; j++)
#pragma unroll
            for (int r = 0; r < 4; r++) acc[i][j][r] = 0.0f;

    for (int k0 = 0; k0 < K; k0 += 16) {
#pragma unroll
        for (int l = 0; l < 2; l++) {
            int it  = t * 2 + l;
            int row = it >> 2;
            int f4  = it & 3;
            int m   = m0 + row;
            float4 v = make_float4(0.f, 0.f, 0.f, 0.f);
            if (m < M) v = *(const float4*)(A + (long long)m * lda + k0 + f4 * 4);
            const float* p = &v.x;
#pragma unroll
            for (int j = 0; j < 4; j++) {
                unsigned h, lo;
                split_tf32(p[j], h, lo);
                AsHi[f4 * 4 + j][row] = h;
                AsLo[f4 * 4 + j][row] = lo;
            }
        }
#pragma unroll
        for (int l = 0; l < 2; l++) {
            int it  = t * 2 + l;
            int row = it >> 2;
            int f4  = it & 3;
            int n   = n0 + row;
            float4 v = make_float4(0.f, 0.f, 0.f, 0.f);
            if (n < N) v = *(const float4*)(B + (long long)n * ldb + k0 + f4 * 4);
            const float* p = &v.x;
#pragma unroll
            for (int j = 0; j < 4; j++) {
                unsigned h, lo;
                split_tf32(p[j], h, lo);
                BsHi[f4 * 4 + j][row] = h;
                BsLo[f4 * 4 + j][row] = lo;
            }
        }
        __syncthreads();

#pragma unroll
        for (int ks = 0; ks < 2; ks++) {
            const int kb = ks * 8;
            unsigned ah[4][4], al[4][4];
#pragma unroll
            for (int mt = 0; mt < 4; mt++) {
                int mr = wm * 64 + mt * 16;
                ah[mt][0] = AsHi[kb + tg    ][mr + g    ];
                ah[mt][1] = AsHi[kb + tg    ][mr + g + 8];
                ah[mt][2] = AsHi[kb + tg + 4][mr + g    ];
                ah[mt][3] = AsHi[kb + tg + 4][mr + g + 8];
                al[mt][0] = AsLo[kb + tg    ][mr + g    ];
                al[mt][1] = AsLo[kb + tg    ][mr + g + 8];
                al[mt][2] = AsLo[kb + tg + 4][mr + g    ];
                al[mt][3] = AsLo[kb + tg + 4][mr + g + 8];
            }
            unsigned bh[4][2], bl[4][2];
#pragma unroll
            for (int nt = 0; nt < 4; nt++) {
                int nc = wn * 32 + nt * 8 + g;
                bh[nt][0] = BsHi[kb + tg    ][nc];
                bh[nt][1] = BsHi[kb + tg + 4][nc];
                bl[nt][0] = BsLo[kb + tg    ][nc];
                bl[nt][1] = BsLo[kb + tg + 4][nc];
            }
#pragma unroll
            for (int mt = 0; mt < 4; mt++)
#pragma unroll
                for (int nt = 0; nt < 4; nt++) {
                    mma1688_tf32(acc[mt][nt], ah[mt], bh[nt]);
                    mma1688_tf32(acc[mt][nt], al[mt], bh[nt]);
                    mma1688_tf32(acc[mt][nt], ah[mt], bl[nt]);
                }
        }
        __syncthreads();
    }

#pragma unroll
    for (int mt = 0; mt < 4; mt++) {
        int m1 = m0 + wm * 64 + mt * 16 + g;
        int m2 = m1 + 8;
#pragma unroll
        for (int nt = 0; nt < 4; nt++) {
            int n1 = n0 + wn * 32 + nt * 8 + 2 * tg;
            float b0v = 0.f, b1v = 0.f;
            if (bias) {
                if (n1     < N) b0v = bias[n1];
                if (n1 + 1 < N) b1v = bias[n1 + 1];
            }
            const float* c = acc[mt][nt];
            float v0, v1;
            if (m1 < M) {
                v0 = c[0] + b0v; v1 = c[1] + b1v;
                if (act == 1) { v0 = gelu_exact(v0); v1 = gelu_exact(v1); }
                if (n1     < N) C[(long long)m1 * ldc + n1    ] = v0;
                if (n1 + 1 < N) C[(long long)m1 * ldc + n1 + 1] = v1;
            }
            if (m2 < M) {
                v0 = c[2] + b0v; v1 = c[3] + b1v;
                if (act == 1) { v0 = gelu_exact(v0); v1 = gelu_exact(v1); }
                if (n1     < N) C[(long long)m2 * ldc + n1    ] = v0;
                if (n1 + 1 < N) C[(long long)m2 * ldc + n1 + 1] = v1;
            }
        }
    }
}

// ---------------- tgt_rep: masked mean over 64 template tokens ---------------
__global__ void tgt_kernel(const float* __restrict__ x, const float* __restrict__ mask)
{
    __shared__ float sm[TTOK];
    int b = blockIdx.x;
    if (threadIdx.x < TTOK) sm[threadIdx.x] = mask[b * TTOK + threadIdx.x];
    __syncthreads();
    for (int c = threadIdx.x; c < CDIM; c += blockDim.x) {
        float s = 0.0f;
        const float* xb = x + (long long)b * NTOK * CDIM + c;
#pragma unroll 8
        for (int t = 0; t < TTOK; t++) s += xb[(long long)t * CDIM] * sm[t];
        g_tgt[b * CDIM + c] = s * (1.0f / (float)TTOK);
    }
}

// ---------------- per-batch MLP1 bias: g_tgtb[b][n] = dp1_b[n] + tgt[b] . W1b[n]
__global__ void tgtb_kernel(const float* __restrict__ dp1_w,
                            const float* __restrict__ dp1_b)
{
    const int warp = threadIdx.x >> 5;
    const int lane = threadIdx.x & 31;
    const int n = blockIdx.x * 8 + warp;          // 48 blocks x 8 warps = 384
    const float* wr = dp1_w + (long long)n * (2 * CDIM) + CDIM;  // tgt half
    float wreg[24];
#pragma unroll
    for (int i = 0; i < 24; i++) wreg[i] = wr[lane + i * 32];
    const float bn = dp1_b[n];
    for (int b = 0; b < BSZ; b++) {
        const float* tg = g_tgt + b * CDIM;
        float s = 0.0f;
#pragma unroll
        for (int i = 0; i < 24; i++) s += wreg[i] * tg[lane + i * 32];
#pragma unroll
        for (int o = 16; o > 0; o >>= 1) s += __shfl_xor_sync(0xffffffffu, s, o);
        if (lane == 0) g_tgtb[b * 384 + n] = s + bn;
    }
}

// ---------------- final MLP layer + argmax + groups + decision out -----------
__global__ void decide_kernel(const float* __restrict__ dp3_w,
                              const float* __restrict__ dp3_b,
                              float* dec_out)
{
    int idx = blockIdx.x * blockDim.x + threadIdx.x;
    if (idx >= BSZ * NTOK) return;
    int b = idx / NTOK, tok = idx % NTOK;
    if (tok < TTOK) { g_grp[idx] = 0; return; }
    int s = tok - TTOK;
    const float* h = g_h2 + ((long long)b * STOK + s) * 192;
    float l0 = dp3_b[0], l1 = dp3_b[1];
#pragma unroll 4
    for (int k = 0; k < 192; k++) {
        float hv = h[k];
        l0 += hv * dp3_w[k];
        l1 += hv * dp3_w[192 + k];
    }
    int cls = (l1 > l0) ? 1 : 0;
    g_grp[idx] = 1 + cls;
    if (dec_out) {
        long long o = ((long long)b * STOK + s) * 2;
        dec_out[o + 0] = (cls == 0) ? 1.0f : 0.0f;
        dec_out[o + 1] = (cls == 1) ? 1.0f : 0.0f;
    }
}

// ---------------- policy softmax (in-place on g_S), one warp per row ---------
__global__ void softmax_policy_kernel()
{
    const int warp = threadIdx.x >> 5;
    const int lane = threadIdx.x & 31;
    const long long r = (long long)blockIdx.x * 4 + warp;
    const long long nrows = (long long)BSZ * HN * NTOK;
    if (r >= nrows) return;
    int bh = (int)(r / NTOK);
    int i  = (int)(r % NTOK);
    int b  = bh / HN;
    float* row = g_S + (long long)bh * NTOK * NTOK + (long long)i * NTOK;
    const int* grp = g_grp + b * NTOK;
    int gi = grp[i];

    float sv[10];
    float mx = -3.4e38f;
#pragma unroll
    for (int l = 0; l < 10; l++) {
        sv[l] = row[lane + l * 32];
        mx = fmaxf(mx, sv[l]);
    }
#pragma unroll
    for (int o = 16; o > 0; o >>= 1) mx = fmaxf(mx, __shfl_xor_sync(0xffffffffu, mx, o));

    float sum = 0.0f;
#pragma unroll
    for (int l = 0; l < 10; l++) {
        int j = lane + l * 32;
        int gj = grp[j];
        float m = (gi == 2 || gj == 2 || gi == gj) ? 1.0f : 0.0f;
        float e = expf(sv[l] - mx) * m;
        sv[l] = e;
        sum += e;
    }
#pragma unroll
    for (int o = 16; o > 0; o >>= 1) sum += __shfl_xor_sync(0xffffffffu, sum, o);

    const float epsn = 1e-6f / (float)NTOK;
    float inv = 1.0f / (sum + 1e-6f);
#pragma unroll
    for (int l = 0; l < 10; l++) row[lane + l * 32] = (sv[l] + epsn) * inv;
}

// ---------------- host launcher ----------------------------------------------
extern "C" void kernel_launch(void* const* d_in, const int* in_sizes, int n_in,
                              void* d_out, int out_size)
{
    const float* x      = (const float*)d_in[0];
    const float* tmask  = (const float*)d_in[1];
    const float* qkv_w  = (const float*)d_in[2];
    const float* qkv_b  = (const float*)d_in[3];
    const float* proj_w = (const float*)d_in[4];
    const float* proj_b = (const float*)d_in[5];
    const float* dp1_w  = (const float*)d_in[6];
    const float* dp1_b  = (const float*)d_in[7];
    const float* dp2_w  = (const float*)d_in[8];
    const float* dp2_b  = (const float*)d_in[9];
    const float* dp3_w  = (const float*)d_in[10];
    const float* dp3_b  = (const float*)d_in[11];
    float* out = (float*)d_out;

    const long long OUT_MAIN = (long long)BSZ * NTOK * CDIM;
    const long long OUT_DEC  = (long long)BSZ * STOK * 2;
    float* dec_out = ((long long)out_size >= OUT_MAIN + OUT_DEC) ? (out + OUT_MAIN) : nullptr;

    float *p_tgtb, *p_h1, *p_h2, *p_qkv, *p_S, *p_ao;
    cudaGetSymbolAddress((void**)&p_tgtb, g_tgtb);
    cudaGetSymbolAddress((void**)&p_h1,  g_h1);
    cudaGetSymbolAddress((void**)&p_h2,  g_h2);
    cudaGetSymbolAddress((void**)&p_qkv, g_qkv);
    cudaGetSymbolAddress((void**)&p_S,   g_S);
    cudaGetSymbolAddress((void**)&p_ao,  g_ao);

    // side stream + events (created once on the eager correctness call,
    // reused as fork/join dependencies inside graph capture)
    static cudaStream_t sB = nullptr;
    static cudaEvent_t evFork = nullptr, evJoin = nullptr;
    if (sB == nullptr) {
        cudaStreamCreateWithFlags(&sB, cudaStreamNonBlocking);
        cudaEventCreateWithFlags(&evFork, cudaEventDisableTiming);
        cudaEventCreateWithFlags(&evJoin, cudaEventDisableTiming);
    }

    // -------- fork: decision-MLP chain on side stream --------
    cudaEventRecord(evFork, 0);
    cudaStreamWaitEvent(sB, evFork, 0);

    tgt_kernel<<<BSZ, 256, 0, sB>>>(x, tmask);
    tgtb_kernel<<<48, 256, 0, sB>>>(dp1_w, dp1_b);

    // MLP1 (tf32x3): per-batch A = x_search[b], K=768 (x half only),
    // per-batch bias = g_tgtb[b], GELU.  grid (3 Ntiles, 2 Mtiles, 32 batches)
    mma_tf32_kernel<<<dim3(3, 2, BSZ), 256, 0, sB>>>(
        x + (long long)TTOK * CDIM, dp1_w, p_tgtb, p_h1,
        STOK, 384, CDIM,
        CDIM, 2 * CDIM, 384, 1,
        (long long)NTOK * CDIM, 384, (long long)STOK * 384);

    // MLP2 (tf32x3) + GELU, single batch
    mma_tf32_kernel<<<dim3(2, (BSZ * STOK) / 128, 1), 256, 0, sB>>>(
        p_h1, dp2_w, dp2_b, p_h2,
        BSZ * STOK, 192, 384,
        384, 384, 192, 1,
        0, 0, 0);

    decide_kernel<<<(BSZ * NTOK + 255) / 256, 256, 0, sB>>>(dp3_w, dp3_b, dec_out);
    cudaEventRecord(evJoin, sB);

    // -------- main stream: attention front-end --------
    // QKV GEMM (bf16x3 tensor)
    mma_gemm_kernel<<<dim3(2304 / 128, (BSZ * NTOK) / 128, 1), 256>>>(
        x, qkv_w, qkv_b, p_qkv,
        BSZ * NTOK, 3 * CDIM, CDIM,
        CDIM, CDIM, 3 * CDIM,
        0, 1, 0, 0, 0, 0, 0, 0, 1.0f);

    // S = Q K^T * scale (bf16x3 tensor), batched over (b,h)
    {
        long long aOuter = (long long)NTOK * 3 * CDIM;
        long long strS   = (long long)NTOK * NTOK;
        mma_gemm_kernel<<<dim3(3, 3, BSZ * HN), 256>>>(
            p_qkv, p_qkv + CDIM, nullptr, p_S,
            NTOK, NTOK, HD,
            3 * CDIM, 3 * CDIM, NTOK,
            0, HN,
            aOuter, HD,
            aOuter, HD,
            (long long)HN * strS, strS,
            0.125f);
    }

    // -------- join: softmax needs g_grp from side stream --------
    cudaStreamWaitEvent(0, evJoin, 0);

    {
        long long nrows = (long long)BSZ * HN * NTOK;
        int blocks = (int)((nrows + 3) / 4);
        softmax_policy_kernel<<<blocks, 128>>>();
    }

    // O = P V (bf16x3 tensor), batched over (b,h)
    {
        long long strS = (long long)NTOK * NTOK;
        mma_gemm_kernel<<<dim3(1, 3, BSZ * HN), 256>>>(
            p_S, p_qkv + 2 * CDIM, nullptr, p_ao,
            NTOK, HD, NTOK,
            NTOK, 3 * CDIM, CDIM,
            1, HN,
            (long long)HN * strS, strS,
            (long long)NTOK * 3 * CDIM, HD,
            (long long)NTOK * CDIM, HD,
            1.0f);
    }

    // output projection (bf16x3 tensor)
    mma_gemm_kernel<<<dim3(CDIM / 128, (BSZ * NTOK) / 128, 1), 256>>>(
        p_ao, proj_w, proj_b, out,
        BSZ * NTOK, CDIM, CDIM,
        CDIM, CDIM, CDIM,
        0, 1, 0, 0, 0, 0, 0, 0, 1.0f);
}

// round 5
// speedup vs baseline: 2.4010x; 1.2272x over previous
#include <cuda_runtime.h>
#include <cuda_bf16.h>
#include <math.h>

// Problem constants
#define BSZ  32
#define NTOK 320
#define CDIM 768
#define HN   12
#define STOK 256
#define TTOK 64
#define HD   64

typedef __nv_bfloat16 bf16;

// ---------------- scratch (__device__ globals: allocation-free) --------------
__device__ float g_tgt [BSZ * CDIM];
__device__ float g_tgtb[BSZ * 384];
__device__ float g_h1 [BSZ * STOK * 384];
__device__ float g_h2 [BSZ * STOK * 192];
__device__ int   g_grp[BSZ * NTOK];

__device__ bf16  g_xhi [BSZ * NTOK * CDIM],      g_xlo [BSZ * NTOK * CDIM];
__device__ bf16  g_qwhi[3 * CDIM * CDIM],        g_qwlo[3 * CDIM * CDIM];
__device__ bf16  g_pwhi[CDIM * CDIM],            g_pwlo[CDIM * CDIM];
__device__ bf16  g_qkvhi[BSZ * NTOK * 3 * CDIM], g_qkvlo[BSZ * NTOK * 3 * CDIM];
__device__ float g_S  [(size_t)BSZ * HN * NTOK * NTOK];
__device__ bf16  g_Phi[(size_t)BSZ * HN * NTOK * NTOK], g_Plo[(size_t)BSZ * HN * NTOK * NTOK];
__device__ bf16  g_aohi[BSZ * NTOK * CDIM],      g_aolo[BSZ * NTOK * CDIM];

__device__ __forceinline__ float gelu_exact(float v) {
    return 0.5f * v * (1.0f + erff(v * 0.70710678118654752f));
}

// ---------------- cp.async helpers -------------------------------------------
__device__ __forceinline__ void cpa16(void* s, const void* g) {
    unsigned sa = (unsigned)__cvta_generic_to_shared(s);
    asm volatile("cp.async.cg.shared.global [%0], [%1], 16;\n" :: "r"(sa), "l"(g));
}
__device__ __forceinline__ void cpa_commit() { asm volatile("cp.async.commit_group;\n"); }
template<int W> __device__ __forceinline__ void cpa_wait() {
    asm volatile("cp.async.wait_group %0;\n" :: "n"(W));
}

__device__ __forceinline__ void mma16816(float* c, const unsigned* a, const unsigned* b) {
    asm volatile(
        "mma.sync.aligned.m16n8k16.row.col.f32.bf16.bf16.f32 "
        "{%0,%1,%2,%3}, {%4,%5,%6,%7}, {%8,%9}, {%0,%1,%2,%3};\n"
        : "+f"(c[0]), "+f"(c[1]), "+f"(c[2]), "+f"(c[3])
        : "r"(a[0]), "r"(a[1]), "r"(a[2]), "r"(a[3]), "r"(b[0]), "r"(b[1]));
}

// ================= pre-split bf16 hi/lo GEMM, cp.async double-buffered =======
// C = alpha * A * op(B) + bias, 3 mma passes (hh + lh + hl).
// A: hi/lo bf16 [M,K] row-major (k contig), lda.
// BMODE 0: B[n][k] k-contig (ldb);  BMODE 1: B[k][n] n-contig (ldb).
// OUTMODE 0: fp32 C;  OUTMODE 2: bf16 hi/lo pair outputs Chi/Clo.
// Warp grid: (8/WN) x WN warps, each warp MT x 4 mma tiles (16x8).
// Block tile: BM=128 rows x BN=WN*32 cols. K-slab 32, 2 stages.
template<int WN, int MT, int BMODE, int OUTMODE>
__global__ __launch_bounds__(256, 2)
void mma_bf16_kernel(const bf16* __restrict__ Ahi, const bf16* __restrict__ Alo,
                     const bf16* __restrict__ Bhi, const bf16* __restrict__ Blo,
                     const float* __restrict__ bias,
                     float* __restrict__ C, bf16* __restrict__ Chi, bf16* __restrict__ Clo,
                     int M, int N, int K, int lda, int ldb, int ldc,
                     int innerCount,
                     long long aOuter, long long aInner,
                     long long bOuter, long long bInner,
                     long long cOuter, long long cInner,
                     float alpha)
{
    constexpr int BN   = WN * 32;
    constexpr int NT   = 4;
    constexpr int ASZ  = 128 * 40;   // elems per (stage,part) A tile
    constexpr int BSZE = BN * 40;    // elems per (stage,part) B tile

    const int z  = blockIdx.z;
    const int zo = z / innerCount, zi = z % innerCount;
    Ahi += (long long)zo * aOuter + (long long)zi * aInner;
    Alo += (long long)zo * aOuter + (long long)zi * aInner;
    Bhi += (long long)zo * bOuter + (long long)zi * bInner;
    Blo += (long long)zo * bOuter + (long long)zi * bInner;
    const long long coff = (long long)zo * cOuter + (long long)zi * cInner;

    extern __shared__ bf16 smem[];
    bf16* sA = smem;                 // [2 stages][2 parts][128*40]
    bf16* sB = smem + 4 * ASZ;       // [2 stages][2 parts][BSZE]

    const int t    = threadIdx.x;
    const int lane = t & 31;
    const int warp = t >> 5;
    const int wm   = warp / WN;
    const int wn   = warp % WN;
    const int g    = lane >> 2;
    const int tg   = lane & 3;
    const int m0   = blockIdx.y * 128;
    const int n0   = blockIdx.x * BN;

    float acc[MT][NT][4];
#pragma unroll
    for (int i = 0; i < MT; i++)
#pragma unroll
        for (int j = 0; j < NT; j++)
#pragma unroll
            for (int r = 0; r < 4; r++) acc[i][j][r] = 0.0f;

    auto loadStage = [&](int st, int k0) {
        // A: 128 rows x 32 k = 512 16B chunks -> 2 rounds
#pragma unroll
        for (int l = 0; l < 2; l++) {
            int idx = t + l * 256;
            int r   = idx >> 2;
            int kc  = (idx & 3) * 8;
            int rg  = m0 + r; if (rg > M - 1) rg = M - 1;
            long long go = (long long)rg * lda + k0 + kc;
            bf16* d0 = sA + (st * 2 + 0) * ASZ + r * 40 + kc;
            bf16* d1 = sA + (st * 2 + 1) * ASZ + r * 40 + kc;
            cpa16(d0, Ahi + go);
            cpa16(d1, Alo + go);
        }
        if (BMODE == 0) {
#pragma unroll
            for (int l = 0; l < WN / 2; l++) {
                int idx = t + l * 256;
                int r   = idx >> 2;
                int kc  = (idx & 3) * 8;
                int ng  = n0 + r; if (ng > N - 1) ng = N - 1;
                long long go = (long long)ng * ldb + k0 + kc;
                cpa16(sB + (st * 2 + 0) * BSZE + r * 40 + kc, Bhi + go);
                cpa16(sB + (st * 2 + 1) * BSZE + r * 40 + kc, Blo + go);
            }
        } else {
            // B[k][n] n-contig: 32 k-rows x BN cols; smem layout [k][BN+16]
#pragma unroll
            for (int l = 0; l < WN / 2; l++) {
                int idx = t + l * 256;
                int kr  = idx / (BN / 8);
                int c8  = (idx % (BN / 8)) * 8;
                long long go = (long long)(k0 + kr) * ldb + n0 + c8;
                cpa16(sB + (st * 2 + 0) * BSZE + kr * (BN + 16) + c8, Bhi + go);
                cpa16(sB + (st * 2 + 1) * BSZE + kr * (BN + 16) + c8, Blo + go);
            }
        }
        cpa_commit();
    };

    const int nslab = K / 32;
    loadStage(0, 0);

    for (int ks = 0; ks < nslab; ks++) {
        const int st = ks & 1;
        if (ks + 1 < nslab) {
            loadStage(st ^ 1, (ks + 1) * 32);
            cpa_wait<1>();
        } else {
            cpa_wait<0>();
        }
        __syncthreads();

        const bf16* aH = sA + (st * 2 + 0) * ASZ;
        const bf16* aL = sA + (st * 2 + 1) * ASZ;
        const bf16* bH = sB + (st * 2 + 0) * BSZE;
        const bf16* bL = sB + (st * 2 + 1) * BSZE;

#pragma unroll
        for (int kh = 0; kh < 2; kh++) {
            const int c0 = kh * 16 + 2 * tg;
            unsigned ah[MT][4], al[MT][4];
#pragma unroll
            for (int mt = 0; mt < MT; mt++) {
                int r0 = wm * (MT * 16) + mt * 16 + g;
                ah[mt][0] = *(const unsigned*)(aH + (long long)r0 * 40 + c0);
                ah[mt][1] = *(const unsigned*)(aH + (long long)(r0 + 8) * 40 + c0);
                ah[mt][2] = *(const unsigned*)(aH + (long long)r0 * 40 + c0 + 8);
                ah[mt][3] = *(const unsigned*)(aH + (long long)(r0 + 8) * 40 + c0 + 8);
                al[mt][0] = *(const unsigned*)(aL + (long long)r0 * 40 + c0);
                al[mt][1] = *(const unsigned*)(aL + (long long)(r0 + 8) * 40 + c0);
                al[mt][2] = *(const unsigned*)(aL + (long long)r0 * 40 + c0 + 8);
                al[mt][3] = *(const unsigned*)(aL + (long long)(r0 + 8) * 40 + c0 + 8);
            }
            unsigned bhf[NT][2], blf[NT][2];
#pragma unroll
            for (int nt = 0; nt < NT; nt++) {
                int nc = wn * 32 + nt * 8 + g;
                if (BMODE == 0) {
                    bhf[nt][0] = *(const unsigned*)(bH + (long long)nc * 40 + c0);
                    bhf[nt][1] = *(const unsigned*)(bH + (long long)nc * 40 + c0 + 8);
                    blf[nt][0] = *(const unsigned*)(bL + (long long)nc * 40 + c0);
                    blf[nt][1] = *(const unsigned*)(bL + (long long)nc * 40 + c0 + 8);
                } else {
                    int kr = kh * 16 + 2 * tg;
                    unsigned h0 = *(const unsigned short*)(bH + (long long)kr * (BN + 16) + nc);
                    unsigned h1 = *(const unsigned short*)(bH + (long long)(kr + 1) * (BN + 16) + nc);
                    unsigned h2 = *(const unsigned short*)(bH + (long long)(kr + 8) * (BN + 16) + nc);
                    unsigned h3 = *(const unsigned short*)(bH + (long long)(kr + 9) * (BN + 16) + nc);
                    bhf[nt][0] = h0 | (h1 << 16);
                    bhf[nt][1] = h2 | (h3 << 16);
                    unsigned l0 = *(const unsigned short*)(bL + (long long)kr * (BN + 16) + nc);
                    unsigned l1 = *(const unsigned short*)(bL + (long long)(kr + 1) * (BN + 16) + nc);
                    unsigned l2 = *(const unsigned short*)(bL + (long long)(kr + 8) * (BN + 16) + nc);
                    unsigned l3 = *(const unsigned short*)(bL + (long long)(kr + 9) * (BN + 16) + nc);
                    blf[nt][0] = l0 | (l1 << 16);
                    blf[nt][1] = l2 | (l3 << 16);
                }
            }
#pragma unroll
            for (int mt = 0; mt < MT; mt++)
#pragma unroll
                for (int nt = 0; nt < NT; nt++) {
                    mma16816(acc[mt][nt], ah[mt], bhf[nt]);
                    mma16816(acc[mt][nt], al[mt], bhf[nt]);
                    mma16816(acc[mt][nt], ah[mt], blf[nt]);
                }
        }
        __syncthreads();
    }

    // ---- epilogue
#pragma unroll
    for (int mt = 0; mt < MT; mt++) {
        int m1 = m0 + wm * (MT * 16) + mt * 16 + g;
        int m2 = m1 + 8;
#pragma unroll
        for (int nt = 0; nt < NT; nt++) {
            int n1 = n0 + wn * 32 + nt * 8 + 2 * tg;
            float b0v = 0.f, b1v = 0.f;
            if (bias) {
                if (n1     < N) b0v = bias[n1];
                if (n1 + 1 < N) b1v = bias[n1 + 1];
            }
            const float* c = acc[mt][nt];
#pragma unroll
            for (int rr = 0; rr < 2; rr++) {
                int m = rr ? m2 : m1;
                if (m >= M) continue;
                float v0 = c[rr * 2 + 0] * alpha + b0v;
                float v1 = c[rr * 2 + 1] * alpha + b1v;
                long long base = coff + (long long)m * ldc;
                if (OUTMODE == 0) {
                    if (n1     < N) C[base + n1    ] = v0;
                    if (n1 + 1 < N) C[base + n1 + 1] = v1;
                } else {
                    if (n1 < N) {
                        bf16 h = __float2bfloat16(v0);
                        Chi[base + n1] = h;
                        Clo[base + n1] = __float2bfloat16(v0 - __bfloat162float(h));
                    }
                    if (n1 + 1 < N) {
                        bf16 h = __float2bfloat16(v1);
                        Chi[base + n1 + 1] = h;
                        Clo[base + n1 + 1] = __float2bfloat16(v1 - __bfloat162float(h));
                    }
                }
            }
        }
    }
}

// ---------------- elementwise fp32 -> bf16 hi/lo split ------------------------
__global__ void split_kernel(const float* __restrict__ src,
                             bf16* __restrict__ hi, bf16* __restrict__ lo,
                             long long n4)
{
    long long i = (long long)blockIdx.x * blockDim.x + threadIdx.x;
    if (i >= n4) return;
    float4 v = ((const float4*)src)[i];
    float p[4] = {v.x, v.y, v.z, v.w};
    unsigned short hs[4], ls[4];
#pragma unroll
    for (int j = 0; j < 4; j++) {
        bf16 h = __float2bfloat16(p[j]);
        bf16 l = __float2bfloat16(p[j] - __bfloat162float(h));
        hs[j] = __bfloat16_as_ushort(h);
        ls[j] = __bfloat16_as_ushort(l);
    }
    ((uint2*)hi)[i] = make_uint2((unsigned)hs[0] | ((unsigned)hs[1] << 16),
                                 (unsigned)hs[2] | ((unsigned)hs[3] << 16));
    ((uint2*)lo)[i] = make_uint2((unsigned)ls[0] | ((unsigned)ls[1] << 16),
                                 (unsigned)ls[2] | ((unsigned)ls[3] << 16));
}

// ================= tf32x3 tensor GEMM (fp32-equivalent, decision path) =======
__device__ __forceinline__ unsigned f2tf32(float x) {
    unsigned r;
    asm("cvt.rna.tf32.f32 %0, %1;" : "=r"(r) : "f"(x));
    return r;
}
__device__ __forceinline__ void split_tf32(float x, unsigned& hi, unsigned& lo) {
    hi = f2tf32(x);
    lo = f2tf32(x - __uint_as_float(hi));
}
__device__ __forceinline__ void mma1688_tf32(float* c, const unsigned* a, const unsigned* b) {
    asm volatile(
        "mma.sync.aligned.m16n8k8.row.col.f32.tf32.tf32.f32 "
        "{%0,%1,%2,%3}, {%4,%5,%6,%7}, {%8,%9}, {%0,%1,%2,%3};\n"
        : "+f"(c[0]), "+f"(c[1]), "+f"(c[2]), "+f"(c[3])
        : "r"(a[0]), "r"(a[1]), "r"(a[2]), "r"(a[3]), "r"(b[0]), "r"(b[1]));
}

#define SPAD 132

__global__ __launch_bounds__(256, 2)
void mma_tf32_kernel(const float* __restrict__ A, const float* __restrict__ B,
                     const float* __restrict__ bias, float* __restrict__ C,
                     int M, int N, int K, int lda, int ldb, int ldc, int act,
                     long long aBatch, long long biasBatch, long long cBatch)
{
    const int z = blockIdx.z;
    A += (long long)z * aBatch;
    C += (long long)z * cBatch;
    if (bias) bias += (long long)z * biasBatch;

    __shared__ unsigned AsHi[16][SPAD], AsLo[16][SPAD];
    __shared__ unsigned BsHi[16][SPAD], BsLo[16][SPAD];

    const int t    = threadIdx.x;
    const int lane = t & 31;
    const int warp = t >> 5;
    const int wm   = warp >> 2;
    const int wn   = warp & 3;
    const int g    = lane >> 2;
    const int tg   = lane & 3;
    const int m0   = blockIdx.y * 128;
    const int n0   = blockIdx.x * 128;

    float acc[4][4][4];
#pragma unroll
    for (int i = 0; i < 4; i++)
#pragma unroll
        for (int j = 0; j < 4; j++)
#pragma unroll
            for (int r = 0; r < 4; r++) acc[i][j][r] = 0.0f;

    for (int k0 = 0; k0 < K; k0 += 16) {
#pragma unroll
        for (int l = 0; l < 2; l++) {
            int it  = t * 2 + l;
            int row = it >> 2;
            int f4  = it & 3;
            int m   = m0 + row;
            float4 v = make_float4(0.f, 0.f, 0.f, 0.f);
            if (m < M) v = *(const float4*)(A + (long long)m * lda + k0 + f4 * 4);
            const float* p = &v.x;
#pragma unroll
            for (int j = 0; j < 4; j++) {
                unsigned h, lo;
                split_tf32(p[j], h, lo);
                AsHi[f4 * 4 + j][row] = h;
                AsLo[f4 * 4 + j][row] = lo;
            }
        }
#pragma unroll
        for (int l = 0; l < 2; l++) {
            int it  = t * 2 + l;
            int row = it >> 2;
            int f4  = it & 3;
            int n   = n0 + row;
            float4 v = make_float4(0.f, 0.f, 0.f, 0.f);
            if (n < N) v = *(const float4*)(B + (long long)n * ldb + k0 + f4 * 4);
            const float* p = &v.x;
#pragma unroll
            for (int j = 0; j < 4; j++) {
                unsigned h, lo;
                split_tf32(p[j], h, lo);
                BsHi[f4 * 4 + j][row] = h;
                BsLo[f4 * 4 + j][row] = lo;
            }
        }
        __syncthreads();

#pragma unroll
        for (int ks = 0; ks < 2; ks++) {
            const int kb = ks * 8;
            unsigned ah[4][4], al[4][4];
#pragma unroll
            for (int mt = 0; mt < 4; mt++) {
                int mr = wm * 64 + mt * 16;
                ah[mt][0] = AsHi[kb + tg    ][mr + g    ];
                ah[mt][1] = AsHi[kb + tg    ][mr + g + 8];
                ah[mt][2] = AsHi[kb + tg + 4][mr + g    ];
                ah[mt][3] = AsHi[kb + tg + 4][mr + g + 8];
                al[mt][0] = AsLo[kb + tg    ][mr + g    ];
                al[mt][1] = AsLo[kb + tg    ][mr + g + 8];
                al[mt][2] = AsLo[kb + tg + 4][mr + g    ];
                al[mt][3] = AsLo[kb + tg + 4][mr + g + 8];
            }
            unsigned bh[4][2], bl[4][2];
#pragma unroll
            for (int nt = 0; nt < 4; nt++) {
                int nc = wn * 32 + nt * 8 + g;
                bh[nt][0] = BsHi[kb + tg    ][nc];
                bh[nt][1] = BsHi[kb + tg + 4][nc];
                bl[nt][0] = BsLo[kb + tg    ][nc];
                bl[nt][1] = BsLo[kb + tg + 4][nc];
            }
#pragma unroll
            for (int mt = 0; mt < 4; mt++)
#pragma unroll
                for (int nt = 0; nt < 4; nt++) {
                    mma1688_tf32(acc[mt][nt], ah[mt], bh[nt]);
                    mma1688_tf32(acc[mt][nt], al[mt], bh[nt]);
                    mma1688_tf32(acc[mt][nt], ah[mt], bl[nt]);
                }
        }
        __syncthreads();
    }

#pragma unroll
    for (int mt = 0; mt < 4; mt++) {
        int m1 = m0 + wm * 64 + mt * 16 + g;
        int m2 = m1 + 8;
#pragma unroll
        for (int nt = 0; nt < 4; nt++) {
            int n1 = n0 + wn * 32 + nt * 8 + 2 * tg;
            float b0v = 0.f, b1v = 0.f;
            if (bias) {
                if (n1     < N) b0v = bias[n1];
                if (n1 + 1 < N) b1v = bias[n1 + 1];
            }
            const float* c = acc[mt][nt];
            float v0, v1;
            if (m1 < M) {
                v0 = c[0] + b0v; v1 = c[1] + b1v;
                if (act == 1) { v0 = gelu_exact(v0); v1 = gelu_exact(v1); }
                if (n1     < N) C[(long long)m1 * ldc + n1    ] = v0;
                if (n1 + 1 < N) C[(long long)m1 * ldc + n1 + 1] = v1;
            }
            if (m2 < M) {
                v0 = c[2] + b0v; v1 = c[3] + b1v;
                if (act == 1) { v0 = gelu_exact(v0); v1 = gelu_exact(v1); }
                if (n1     < N) C[(long long)m2 * ldc + n1    ] = v0;
                if (n1 + 1 < N) C[(long long)m2 * ldc + n1 + 1] = v1;
            }
        }
    }
}

// ---------------- tgt_rep: masked mean over 64 template tokens ---------------
__global__ void tgt_kernel(const float* __restrict__ x, const float* __restrict__ mask)
{
    __shared__ float sm[TTOK];
    int b = blockIdx.x;
    if (threadIdx.x < TTOK) sm[threadIdx.x] = mask[b * TTOK + threadIdx.x];
    __syncthreads();
    for (int c = threadIdx.x; c < CDIM; c += blockDim.x) {
        float s = 0.0f;
        const float* xb = x + (long long)b * NTOK * CDIM + c;
#pragma unroll 8
        for (int t = 0; t < TTOK; t++) s += xb[(long long)t * CDIM] * sm[t];
        g_tgt[b * CDIM + c] = s * (1.0f / (float)TTOK);
    }
}

// ---------------- per-batch MLP1 bias ----------------------------------------
__global__ void tgtb_kernel(const float* __restrict__ dp1_w,
                            const float* __restrict__ dp1_b)
{
    const int warp = threadIdx.x >> 5;
    const int lane = threadIdx.x & 31;
    const int n = blockIdx.x * 8 + warp;
    const float* wr = dp1_w + (long long)n * (2 * CDIM) + CDIM;
    float wreg[24];
#pragma unroll
    for (int i = 0; i < 24; i++) wreg[i] = wr[lane + i * 32];
    const float bn = dp1_b[n];
    for (int b = 0; b < BSZ; b++) {
        const float* tg = g_tgt + b * CDIM;
        float s = 0.0f;
#pragma unroll
        for (int i = 0; i < 24; i++) s += wreg[i] * tg[lane + i * 32];
#pragma unroll
        for (int o = 16; o > 0; o >>= 1) s += __shfl_xor_sync(0xffffffffu, s, o);
        if (lane == 0) g_tgtb[b * 384 + n] = s + bn;
    }
}

// ---------------- final MLP layer + argmax + groups + decision out -----------
__global__ void decide_kernel(const float* __restrict__ dp3_w,
                              const float* __restrict__ dp3_b,
                              float* dec_out)
{
    int idx = blockIdx.x * blockDim.x + threadIdx.x;
    if (idx >= BSZ * NTOK) return;
    int b = idx / NTOK, tok = idx % NTOK;
    if (tok < TTOK) { g_grp[idx] = 0; return; }
    int s = tok - TTOK;
    const float* h = g_h2 + ((long long)b * STOK + s) * 192;
    float l0 = dp3_b[0], l1 = dp3_b[1];
#pragma unroll 4
    for (int k = 0; k < 192; k++) {
        float hv = h[k];
        l0 += hv * dp3_w[k];
        l1 += hv * dp3_w[192 + k];
    }
    int cls = (l1 > l0) ? 1 : 0;
    g_grp[idx] = 1 + cls;
    if (dec_out) {
        long long o = ((long long)b * STOK + s) * 2;
        dec_out[o + 0] = (cls == 0) ? 1.0f : 0.0f;
        dec_out[o + 1] = (cls == 1) ? 1.0f : 0.0f;
    }
}

// ---------------- policy softmax: S fp32 -> P hi/lo bf16 ---------------------
__global__ void softmax_policy_kernel()
{
    const int warp = threadIdx.x >> 5;
    const int lane = threadIdx.x & 31;
    const long long r = (long long)blockIdx.x * 4 + warp;
    const long long nrows = (long long)BSZ * HN * NTOK;
    if (r >= nrows) return;
    int bh = (int)(r / NTOK);
    int i  = (int)(r % NTOK);
    int b  = bh / HN;
    const long long rowbase = (long long)bh * NTOK * NTOK + (long long)i * NTOK;
    const float* row = g_S + rowbase;
    const int* grp = g_grp + b * NTOK;
    int gi = grp[i];

    float sv[10];
    float mx = -3.4e38f;
#pragma unroll
    for (int l = 0; l < 10; l++) {
        sv[l] = row[lane + l * 32];
        mx = fmaxf(mx, sv[l]);
    }
#pragma unroll
    for (int o = 16; o > 0; o >>= 1) mx = fmaxf(mx, __shfl_xor_sync(0xffffffffu, mx, o));

    float sum = 0.0f;
#pragma unroll
    for (int l = 0; l < 10; l++) {
        int j = lane + l * 32;
        int gj = grp[j];
        float m = (gi == 2 || gj == 2 || gi == gj) ? 1.0f : 0.0f;
        float e = expf(sv[l] - mx) * m;
        sv[l] = e;
        sum += e;
    }
#pragma unroll
    for (int o = 16; o > 0; o >>= 1) sum += __shfl_xor_sync(0xffffffffu, sum, o);

    const float epsn = 1e-6f / (float)NTOK;
    float inv = 1.0f / (sum + 1e-6f);
#pragma unroll
    for (int l = 0; l < 10; l++) {
        float v = (sv[l] + epsn) * inv;
        bf16 h = __float2bfloat16(v);
        long long off = rowbase + lane + l * 32;
        g_Phi[off] = h;
        g_Plo[off] = __float2bfloat16(v - __bfloat162float(h));
    }
}

// ---------------- host launcher ----------------------------------------------
extern "C" void kernel_launch(void* const* d_in, const int* in_sizes, int n_in,
                              void* d_out, int out_size)
{
    const float* x      = (const float*)d_in[0];
    const float* tmask  = (const float*)d_in[1];
    const float* qkv_w  = (const float*)d_in[2];
    const float* qkv_b  = (const float*)d_in[3];
    const float* proj_w = (const float*)d_in[4];
    const float* proj_b = (const float*)d_in[5];
    const float* dp1_w  = (const float*)d_in[6];
    const float* dp1_b  = (const float*)d_in[7];
    const float* dp2_w  = (const float*)d_in[8];
    const float* dp2_b  = (const float*)d_in[9];
    const float* dp3_w  = (const float*)d_in[10];
    const float* dp3_b  = (const float*)d_in[11];
    float* out = (float*)d_out;

    const long long OUT_MAIN = (long long)BSZ * NTOK * CDIM;
    const long long OUT_DEC  = (long long)BSZ * STOK * 2;
    float* dec_out = ((long long)out_size >= OUT_MAIN + OUT_DEC) ? (out + OUT_MAIN) : nullptr;

    float *p_tgtb, *p_h1, *p_h2, *p_S;
    bf16 *p_xhi, *p_xlo, *p_qwhi, *p_qwlo, *p_pwhi, *p_pwlo;
    bf16 *p_qkvhi, *p_qkvlo, *p_Phi, *p_Plo, *p_aohi, *p_aolo;
    cudaGetSymbolAddress((void**)&p_tgtb, g_tgtb);
    cudaGetSymbolAddress((void**)&p_h1,   g_h1);
    cudaGetSymbolAddress((void**)&p_h2,   g_h2);
    cudaGetSymbolAddress((void**)&p_S,    g_S);
    cudaGetSymbolAddress((void**)&p_xhi,  g_xhi);
    cudaGetSymbolAddress((void**)&p_xlo,  g_xlo);
    cudaGetSymbolAddress((void**)&p_qwhi, g_qwhi);
    cudaGetSymbolAddress((void**)&p_qwlo, g_qwlo);
    cudaGetSymbolAddress((void**)&p_pwhi, g_pwhi);
    cudaGetSymbolAddress((void**)&p_pwlo, g_pwlo);
    cudaGetSymbolAddress((void**)&p_qkvhi, g_qkvhi);
    cudaGetSymbolAddress((void**)&p_qkvlo, g_qkvlo);
    cudaGetSymbolAddress((void**)&p_Phi,  g_Phi);
    cudaGetSymbolAddress((void**)&p_Plo,  g_Plo);
    cudaGetSymbolAddress((void**)&p_aohi, g_aohi);
    cudaGetSymbolAddress((void**)&p_aolo, g_aolo);

    // one-time setup: side stream, events, smem attrs
    static cudaStream_t sB = nullptr;
    static cudaEvent_t evFork = nullptr, evJoin = nullptr;
    if (sB == nullptr) {
        cudaStreamCreateWithFlags(&sB, cudaStreamNonBlocking);
        cudaEventCreateWithFlags(&evFork, cudaEventDisableTiming);
        cudaEventCreateWithFlags(&evJoin, cudaEventDisableTiming);
        cudaFuncSetAttribute(mma_bf16_kernel<4, 4, 0, 2>,
                             cudaFuncAttributeMaxDynamicSharedMemorySize, 81920);
        cudaFuncSetAttribute(mma_bf16_kernel<4, 4, 0, 0>,
                             cudaFuncAttributeMaxDynamicSharedMemorySize, 81920);
        cudaFuncSetAttribute(mma_bf16_kernel<2, 2, 1, 2>,
                             cudaFuncAttributeMaxDynamicSharedMemorySize, 61440);
    }
    const int SMEM_A = 81920;   // (2*2*128*40 + 2*2*128*40) * 2B
    const int SMEM_B = 61440;   // (2*2*128*40 + 2*2*64*40) * 2B

    // -------- fork: decision-MLP chain on side stream --------
    cudaEventRecord(evFork, 0);
    cudaStreamWaitEvent(sB, evFork, 0);

    tgt_kernel<<<BSZ, 256, 0, sB>>>(x, tmask);
    tgtb_kernel<<<48, 256, 0, sB>>>(dp1_w, dp1_b);
    mma_tf32_kernel<<<dim3(3, 2, BSZ), 256, 0, sB>>>(
        x + (long long)TTOK * CDIM, dp1_w, p_tgtb, p_h1,
        STOK, 384, CDIM,
        CDIM, 2 * CDIM, 384, 1,
        (long long)NTOK * CDIM, 384, (long long)STOK * 384);
    mma_tf32_kernel<<<dim3(2, (BSZ * STOK) / 128, 1), 256, 0, sB>>>(
        p_h1, dp2_w, dp2_b, p_h2,
        BSZ * STOK, 192, 384,
        384, 384, 192, 1,
        0, 0, 0);
    decide_kernel<<<(BSZ * NTOK + 255) / 256, 256, 0, sB>>>(dp3_w, dp3_b, dec_out);
    cudaEventRecord(evJoin, sB);

    // -------- main stream: pre-splits --------
    split_kernel<<<(int)(((long long)BSZ * NTOK * CDIM / 4 + 255) / 256), 256>>>(
        x, p_xhi, p_xlo, (long long)BSZ * NTOK * CDIM / 4);
    split_kernel<<<(3 * CDIM * CDIM / 4 + 255) / 256, 256>>>(
        qkv_w, p_qwhi, p_qwlo, 3 * CDIM * CDIM / 4);
    split_kernel<<<(CDIM * CDIM / 4 + 255) / 256, 256>>>(
        proj_w, p_pwhi, p_pwlo, CDIM * CDIM / 4);

    // QKV GEMM: [10240,768] x [2304,768]^T -> qkv hi/lo
    mma_bf16_kernel<4, 4, 0, 2><<<dim3(2304 / 128, (BSZ * NTOK) / 128, 1), 256, SMEM_A>>>(
        p_xhi, p_xlo, p_qwhi, p_qwlo, qkv_b,
        nullptr, p_qkvhi, p_qkvlo,
        BSZ * NTOK, 3 * CDIM, CDIM,
        CDIM, CDIM, 3 * CDIM,
        1, 0, 0, 0, 0, 0, 0, 1.0f);

    // S = Q K^T * scale -> fp32, batched over (b,h)
    {
        long long aOuter = (long long)NTOK * 3 * CDIM;
        long long strS   = (long long)NTOK * NTOK;
        mma_bf16_kernel<4, 4, 0, 0><<<dim3(3, 3, BSZ * HN), 256, SMEM_A>>>(
            p_qkvhi, p_qkvlo, p_qkvhi + CDIM, p_qkvlo + CDIM, nullptr,
            p_S, nullptr, nullptr,
            NTOK, NTOK, HD,
            3 * CDIM, 3 * CDIM, NTOK,
            HN,
            aOuter, HD,
            aOuter, HD,
            (long long)HN * strS, strS,
            0.125f);
    }

    // -------- join: softmax needs g_grp from side stream --------
    cudaStreamWaitEvent(0, evJoin, 0);

    {
        long long nrows = (long long)BSZ * HN * NTOK;
        int blocks = (int)((nrows + 3) / 4);
        softmax_policy_kernel<<<blocks, 128>>>();
    }

    // O = P V -> ao hi/lo, batched over (b,h); V consumed as B[k][n]
    {
        long long strS = (long long)NTOK * NTOK;
        mma_bf16_kernel<2, 2, 1, 2><<<dim3(1, 3, BSZ * HN), 256, SMEM_B>>>(
            p_Phi, p_Plo, p_qkvhi + 2 * CDIM, p_qkvlo + 2 * CDIM, nullptr,
            nullptr, p_aohi, p_aolo,
            NTOK, HD, NTOK,
            NTOK, 3 * CDIM, CDIM,
            HN,
            (long long)HN * strS, strS,
            (long long)NTOK * 3 * CDIM, HD,
            (long long)NTOK * CDIM, HD,
            1.0f);
    }

    // output projection: [10240,768] x [768,768]^T + bias -> d_out (fp32)
    mma_bf16_kernel<4, 4, 0, 0><<<dim3(CDIM / 128, (BSZ * NTOK) / 128, 1), 256, SMEM_A>>>(
        p_aohi, p_aolo, p_pwhi, p_pwlo, proj_b,
        out, nullptr, nullptr,
        BSZ * NTOK, CDIM, CDIM,
        CDIM, CDIM, CDIM,
        1, 0, 0, 0, 0, 0, 0, 1.0f);
}